// round 9
// baseline (speedup 1.0000x reference)
#include <cuda_runtime.h>
#include <cuda_fp16.h>
#include <cstdint>

#define BATCH 2
#define SEQ 4096
#define NH 16
#define DK 64
#define DM 1024
#define L2E 1.4426950408889634f

#define QKV_ELEMS ((size_t)BATCH * NH * SEQ * DK)

// ---------------- scratch (no allocation allowed) ----------------
__device__ unsigned short g_Qh[QKV_ELEMS];
__device__ unsigned short g_Kh[QKV_ELEMS];
__device__ unsigned short g_Vh[QKV_ELEMS];
__device__ unsigned short g_Ah[(size_t)BATCH * SEQ * DM];
__device__ unsigned short g_Xh[(size_t)BATCH * SEQ * DM];
__device__ unsigned short g_Wh[(size_t)4 * DM * DM];

// ---------------- helpers ----------------
__device__ __forceinline__ uint32_t pkh(float lo, float hi) {
    uint32_t r;
    asm("cvt.rn.f16x2.f32 %0, %1, %2;" : "=r"(r) : "f"(hi), "f"(lo));
    return r;
}
__device__ __forceinline__ uint32_t smem_u32(const void* p) {
    uint32_t a;
    asm("{ .reg .u64 t; cvta.to.shared.u64 t, %1; cvt.u32.u64 %0, t; }"
        : "=r"(a) : "l"(p));
    return a;
}
__device__ __forceinline__ void cp16(uint32_t dst, const void* src) {
    asm volatile("cp.async.cg.shared.global [%0], [%1], 16;" :: "r"(dst), "l"(src));
}
__device__ __forceinline__ void cp_commit() {
    asm volatile("cp.async.commit_group;" ::: "memory");
}
template <int N>
__device__ __forceinline__ void cp_wait() {
    asm volatile("cp.async.wait_group %0;" :: "n"(N) : "memory");
}
__device__ __forceinline__ uint32_t swzb(uint32_t o) {   // 128B-row swizzle
    return o ^ ((o >> 3) & 0x70);
}
__device__ __forceinline__ void ldsm4(uint32_t& r0, uint32_t& r1, uint32_t& r2,
                                      uint32_t& r3, uint32_t a) {
    asm volatile("ldmatrix.sync.aligned.m8n8.x4.shared.b16 {%0,%1,%2,%3}, [%4];"
                 : "=r"(r0), "=r"(r1), "=r"(r2), "=r"(r3) : "r"(a));
}
__device__ __forceinline__ void ldsm4t(uint32_t& r0, uint32_t& r1, uint32_t& r2,
                                       uint32_t& r3, uint32_t a) {
    asm volatile("ldmatrix.sync.aligned.m8n8.x4.trans.shared.b16 {%0,%1,%2,%3}, [%4];"
                 : "=r"(r0), "=r"(r1), "=r"(r2), "=r"(r3) : "r"(a));
}
__device__ __forceinline__ void mma16(float c[4], uint32_t a0, uint32_t a1,
                                      uint32_t a2, uint32_t a3,
                                      uint32_t b0, uint32_t b1) {
    asm volatile(
        "mma.sync.aligned.m16n8k16.row.col.f32.f16.f16.f32 "
        "{%0,%1,%2,%3}, {%4,%5,%6,%7}, {%8,%9}, {%0,%1,%2,%3};"
        : "+f"(c[0]), "+f"(c[1]), "+f"(c[2]), "+f"(c[3])
        : "r"(a0), "r"(a1), "r"(a2), "r"(a3), "r"(b0), "r"(b1));
}

// ---------------- convert x + all W to fp16 ----------------
__global__ __launch_bounds__(256) void round_f16_kernel(
    const float* __restrict__ x, const float* __restrict__ Wq,
    const float* __restrict__ Wk, const float* __restrict__ Wv,
    const float* __restrict__ Wo) {
    size_t i4 = (size_t)blockIdx.x * 256 + threadIdx.x;  // float4 index
    const float4* src;
    uint2* dst;
    if (i4 < 2097152) {
        src = (const float4*)x + i4;
        dst = (uint2*)g_Xh + i4;
    } else {
        size_t r = i4 - 2097152;
        int j = (int)(r >> 18);
        size_t o = r & 262143;
        const float* w = (j == 0) ? Wq : (j == 1) ? Wk : (j == 2) ? Wv : Wo;
        src = (const float4*)w + o;
        dst = (uint2*)g_Wh + (size_t)j * 262144 + o;
    }
    float4 v = *src;
    *dst = make_uint2(pkh(v.x, v.y), pkh(v.z, v.w));
}

// ---------------- fp16 mma GEMM: C = A(Mx1024) * W(1024x1024)^T ------------
// tile 128x128, k-block 32, 3-stage cp.async, ldmatrix operands.
// smem/stage: A 128x40h (10240B) + W 128x40h.  MODE as before.
#define GSTAGE 20480
#define GEMM_SMEM (3 * GSTAGE)

template <int MODE>
__global__ __launch_bounds__(256, 2) void gemm_f16(
    const unsigned short* __restrict__ Abase,
    const unsigned short* __restrict__ Wbase,
    void* C0, void* C1, void* C2) {
    extern __shared__ __align__(16) char smraw[];
    const uint32_t smb = smem_u32(smraw);

    const int tid = threadIdx.x, wid = tid >> 5, lane = tid & 31;
    const int g = lane >> 2, tig = lane & 3;
    const int wm = (wid & 1) * 64, wn = (wid >> 1) * 32;
    const int z = blockIdx.z;
    const int m0 = blockIdx.y * 128, n0 = blockIdx.x * 128;
    const unsigned short* W = Wbase + (size_t)z * (DM * DM);
    void* C = (z == 0) ? C0 : (z == 1) ? C1 : C2;

    float acc[4][4][4];
#pragma unroll
    for (int mt = 0; mt < 4; mt++)
#pragma unroll
        for (int nt = 0; nt < 4; nt++)
#pragma unroll
            for (int k = 0; k < 4; k++) acc[mt][nt][k] = 0.f;

    const int a_r = (lane & 7) + ((lane >> 3) & 1) * 8;
    const int a_c = (lane >> 4) << 3;
    const int lr2 = tid >> 2, lc2 = (tid & 3) * 8;

    auto fill = [&](int s) {
        const uint32_t st = smb + (uint32_t)(s % 3) * GSTAGE;
        const int kb = s * 32;
#pragma unroll
        for (int i = 0; i < 2; i++) {
            int r = lr2 + i * 64;
            cp16(st + r * 80 + (lc2 >> 3) * 16,
                 Abase + (size_t)(m0 + r) * DM + kb + lc2);
        }
#pragma unroll
        for (int i = 0; i < 2; i++) {
            int r = lr2 + i * 64;
            cp16(st + 10240 + r * 80 + (lc2 >> 3) * 16,
                 W + (size_t)(n0 + r) * DM + kb + lc2);
        }
        cp_commit();
    };

    fill(0);
    fill(1);

    for (int s = 0; s < 32; s++) {
        if (s + 2 < 32) fill(s + 2);
        cp_wait<2>();
        __syncthreads();
        const uint32_t asb = smb + (uint32_t)(s % 3) * GSTAGE;
        const uint32_t wsb = asb + 10240;

#pragma unroll
        for (int kk = 0; kk < 32; kk += 16) {
            uint32_t a[4][4], b[2][4];
#pragma unroll
            for (int mt = 0; mt < 4; mt++) {
                int ar = wm + mt * 16 + a_r;
                ldsm4(a[mt][0], a[mt][1], a[mt][2], a[mt][3],
                      asb + (uint32_t)(ar * 40 + kk + a_c) * 2);
            }
#pragma unroll
            for (int j = 0; j < 2; j++) {
                int nr = wn + j * 16 + (lane & 7) + ((lane >> 4) << 3);
                int kc = kk + ((lane >> 3) & 1) * 8;
                ldsm4(b[j][0], b[j][1], b[j][2], b[j][3],
                      wsb + (uint32_t)(nr * 40 + kc) * 2);
            }
#pragma unroll
            for (int mt = 0; mt < 4; mt++)
#pragma unroll
                for (int j = 0; j < 2; j++) {
                    mma16(acc[mt][2 * j], a[mt][0], a[mt][1], a[mt][2], a[mt][3],
                          b[j][0], b[j][1]);
                    mma16(acc[mt][2 * j + 1], a[mt][0], a[mt][1], a[mt][2], a[mt][3],
                          b[j][2], b[j][3]);
                }
        }
        __syncthreads();
    }

#pragma unroll
    for (int mt = 0; mt < 4; mt++) {
#pragma unroll
        for (int nt = 0; nt < 4; nt++) {
            int r0 = m0 + wm + mt * 16 + g;
            int r1 = r0 + 8;
            int cc = n0 + wn + nt * 8 + 2 * tig;
            if (MODE == 0) {
                float* Cf = (float*)C;
                *(float2*)&Cf[(size_t)r0 * DM + cc] =
                    make_float2(acc[mt][nt][0], acc[mt][nt][1]);
                *(float2*)&Cf[(size_t)r1 * DM + cc] =
                    make_float2(acc[mt][nt][2], acc[mt][nt][3]);
            } else {
                unsigned short* Ch = (unsigned short*)C;
                int h = cc >> 6, d = cc & 63;
                int b0i = r0 >> 12, s0 = r0 & (SEQ - 1);
                int b1i = r1 >> 12, s1 = r1 & (SEQ - 1);
                *(uint32_t*)(Ch + ((size_t)(b0i * NH + h) * SEQ + s0) * DK + d) =
                    pkh(acc[mt][nt][0], acc[mt][nt][1]);
                *(uint32_t*)(Ch + ((size_t)(b1i * NH + h) * SEQ + s1) * DK + d) =
                    pkh(acc[mt][nt][2], acc[mt][nt][3]);
            }
        }
    }
}

// ---------------- RoPE (fp16 in-place; folds Q-scale) ----------------
__global__ void rope_kernel(const int* __restrict__ pos) {
    const int NPAIR = BATCH * NH * SEQ * (DK / 2);
    int i = blockIdx.x * blockDim.x + threadIdx.x;
    if (i >= NPAIR) return;
    int j = i & 31;
    int s = (i >> 5) & (SEQ - 1);
    int h = (i >> 17) & (NH - 1);
    int b = i >> 21;

    const bool isQ = (blockIdx.y == 0);
    uint32_t* ptr32 = (uint32_t*)(isQ ? g_Qh : g_Kh);
    int p = pos[b * SEQ + s];
    float freq = exp2f(-(float)j * (13.287712379549449f / 32.f));
    float ang = (float)p * freq;
    float sn, cs;
    sincosf(ang, &sn, &cs);

    size_t idx = ((size_t)(b * NH + h) * SEQ + s) * 32 + j;
    uint32_t pv = ptr32[idx];
    __half2 hv = *(__half2*)&pv;
    float e = __half2float(__low2half(hv));
    float o = __half2float(__high2half(hv));
    float ne = e * cs - o * sn;
    float no = e * sn + o * cs;
    if (isQ) {
        const float qscale = 0.125f * L2E;
        ne *= qscale;
        no *= qscale;
    }
    ptr32[idx] = pkh(ne, no);
}

// ---------------- causal flash attention, fp16 + swizzled smem -------------
// Br=Bc=64, 128 threads (4 warps x 16 rows). Q frags in registers.
// smem: 5 tiles x 8192B (Q | K0 K1 | V0 V1), 128B swizzled rows -> 40960 B.
#define AT_Q 0
#define AT_K 8192
#define AT_V 24576
#define ATT_SMEM 40960

__global__ __launch_bounds__(128, 5) void attn_f16(float* dummy) {
    extern __shared__ __align__(16) char asm_raw[];
    const uint32_t smb = smem_u32(asm_raw);

    const int qt = 63 - (int)blockIdx.x;
    const int h = blockIdx.y;
    const int b = blockIdx.z;
    const int tid = threadIdx.x;
    const int wid = tid >> 5, lane = tid & 31;
    const int g = lane >> 2, tig = lane & 3;
    const int wr = wid * 16;

    const size_t bh = (size_t)(b * NH + h) * SEQ;
    const unsigned short* Qb = g_Qh + (bh + (size_t)qt * 64) * DK;
    const unsigned short* Kb = g_Kh + bh * DK;
    const unsigned short* Vb = g_Vh + bh * DK;

    const int l_r = (lane & 7) + ((lane >> 3) & 1) * 8;
    const int l_c8 = (lane >> 4) << 3;

    auto prefetch = [&](int kt, int buf) {
        const uint32_t kst = smb + AT_K + buf * 8192;
        const uint32_t vst = smb + AT_V + buf * 8192;
#pragma unroll
        for (int i = 0; i < 4; i++) {
            int q = tid + i * 128;
            int r = q >> 3, c = q & 7;
            cp16(kst + swzb(r * 128 + c * 16),
                 Kb + (size_t)(kt * 64 + r) * DK + c * 8);
        }
#pragma unroll
        for (int i = 0; i < 4; i++) {
            int q = tid + i * 128;
            int r = q >> 3, c = q & 7;
            cp16(vst + swzb(r * 128 + c * 16),
                 Vb + (size_t)(kt * 64 + r) * DK + c * 8);
        }
        cp_commit();
    };

    // Q tile -> swizzled smem (once)
#pragma unroll
    for (int p = 0; p < 4; p++) {
        int idx = p * 128 + tid;
        int r = idx >> 3, c = idx & 7;
        *(uint4*)(asm_raw + swzb(r * 128 + c * 16)) =
            *(const uint4*)(Qb + (size_t)r * DK + c * 8);
    }
    prefetch(0, 0);
    __syncthreads();

    // hoist Q fragments (4 k-chunks of 16)
    uint32_t qf[4][4];
#pragma unroll
    for (int kq = 0; kq < 4; kq++) {
        int qr = wr + l_r;
        int qcb = (kq * 16 + l_c8) * 2;
        ldsm4(qf[kq][0], qf[kq][1], qf[kq][2], qf[kq][3],
              smb + swzb((uint32_t)(qr * 128 + qcb)));
    }

    float oacc[8][4];
    float m0 = -1e30f, m1 = -1e30f, l0 = 0.f, l1 = 0.f;
#pragma unroll
    for (int nt = 0; nt < 8; nt++)
#pragma unroll
        for (int k = 0; k < 4; k++) oacc[nt][k] = 0.f;

    const int ntiles = qt + 1;
    for (int kt = 0; kt < ntiles; kt++) {
        const int buf = kt & 1;
        __syncthreads();
        if (kt + 1 < ntiles) {
            prefetch(kt + 1, buf ^ 1);
            cp_wait<1>();
        } else {
            cp_wait<0>();
        }
        __syncthreads();

        const uint32_t ksb = smb + AT_K + buf * 8192;
        const uint32_t vsb = smb + AT_V + buf * 8192;

        // S = Q K^T
        float sacc[8][4];
#pragma unroll
        for (int nt = 0; nt < 8; nt++)
#pragma unroll
            for (int k = 0; k < 4; k++) sacc[nt][k] = 0.f;

#pragma unroll
        for (int kq = 0; kq < 4; kq++) {
            const int kk = kq * 16;
#pragma unroll
            for (int j = 0; j < 4; j++) {
                int nr = j * 16 + (lane & 7) + l_c8;
                int kcb = (kk + ((lane >> 3) & 1) * 8) * 2;
                uint32_t b0, b1, b2, b3;
                ldsm4(b0, b1, b2, b3, ksb + swzb((uint32_t)(nr * 128 + kcb)));
                mma16(sacc[2 * j], qf[kq][0], qf[kq][1], qf[kq][2], qf[kq][3], b0, b1);
                mma16(sacc[2 * j + 1], qf[kq][0], qf[kq][1], qf[kq][2], qf[kq][3], b2, b3);
            }
        }

        if (kt == qt) {  // causal mask on diagonal tile
#pragma unroll
            for (int nt = 0; nt < 8; nt++) {
                int c0 = nt * 8 + 2 * tig, c1 = c0 + 1;
                if (c0 > wr + g) sacc[nt][0] = -1e30f;
                if (c1 > wr + g) sacc[nt][1] = -1e30f;
                if (c0 > wr + g + 8) sacc[nt][2] = -1e30f;
                if (c1 > wr + g + 8) sacc[nt][3] = -1e30f;
            }
        }

        // online softmax (rows wr+g, wr+g+8)
        float tm0 = -1e30f, tm1 = -1e30f;
#pragma unroll
        for (int nt = 0; nt < 8; nt++) {
            tm0 = fmaxf(tm0, fmaxf(sacc[nt][0], sacc[nt][1]));
            tm1 = fmaxf(tm1, fmaxf(sacc[nt][2], sacc[nt][3]));
        }
        tm0 = fmaxf(tm0, __shfl_xor_sync(0xffffffffu, tm0, 1));
        tm0 = fmaxf(tm0, __shfl_xor_sync(0xffffffffu, tm0, 2));
        tm1 = fmaxf(tm1, __shfl_xor_sync(0xffffffffu, tm1, 1));
        tm1 = fmaxf(tm1, __shfl_xor_sync(0xffffffffu, tm1, 2));

        float mn0 = fmaxf(m0, tm0), mn1 = fmaxf(m1, tm1);
        float al0 = exp2f(m0 - mn0), al1 = exp2f(m1 - mn1);
        m0 = mn0; m1 = mn1;

        float rs0 = 0.f, rs1 = 0.f;
#pragma unroll
        for (int nt = 0; nt < 8; nt++) {
            sacc[nt][0] = exp2f(sacc[nt][0] - mn0);
            sacc[nt][1] = exp2f(sacc[nt][1] - mn0);
            sacc[nt][2] = exp2f(sacc[nt][2] - mn1);
            sacc[nt][3] = exp2f(sacc[nt][3] - mn1);
            rs0 += sacc[nt][0] + sacc[nt][1];
            rs1 += sacc[nt][2] + sacc[nt][3];
        }
        rs0 += __shfl_xor_sync(0xffffffffu, rs0, 1);
        rs0 += __shfl_xor_sync(0xffffffffu, rs0, 2);
        rs1 += __shfl_xor_sync(0xffffffffu, rs1, 1);
        rs1 += __shfl_xor_sync(0xffffffffu, rs1, 2);
        l0 = l0 * al0 + rs0;
        l1 = l1 * al1 + rs1;

#pragma unroll
        for (int nt = 0; nt < 8; nt++) {
            oacc[nt][0] *= al0; oacc[nt][1] *= al0;
            oacc[nt][2] *= al1; oacc[nt][3] *= al1;
        }

        // O += P V : P direct from registers (fp16), V via ldmatrix.trans
#pragma unroll
        for (int kc = 0; kc < 64; kc += 16) {
            const int e = kc >> 3;
            uint32_t a0 = pkh(sacc[e][0], sacc[e][1]);
            uint32_t a1 = pkh(sacc[e][2], sacc[e][3]);
            uint32_t a2 = pkh(sacc[e + 1][0], sacc[e + 1][1]);
            uint32_t a3 = pkh(sacc[e + 1][2], sacc[e + 1][3]);
#pragma unroll
            for (int j = 0; j < 4; j++) {
                int vr = kc + l_r;
                int vcb = (j * 16 + l_c8) * 2;
                uint32_t b0, b1, b2, b3;
                ldsm4t(b0, b1, b2, b3, vsb + swzb((uint32_t)(vr * 128 + vcb)));
                mma16(oacc[2 * j], a0, a1, a2, a3, b0, b1);
                mma16(oacc[2 * j + 1], a0, a1, a2, a3, b2, b3);
            }
        }
    }

    // normalize + fp16 write [b][s][h][d] (feeds Wo GEMM)
    float inv0 = 1.f / l0, inv1 = 1.f / l1;
    int sg0 = qt * 64 + wr + g, sg1 = sg0 + 8;
#pragma unroll
    for (int nt = 0; nt < 8; nt++) {
        int d = nt * 8 + 2 * tig;
        *(uint32_t*)(g_Ah + (((size_t)b * SEQ + sg0) * NH + h) * DK + d) =
            pkh(oacc[nt][0] * inv0, oacc[nt][1] * inv0);
        *(uint32_t*)(g_Ah + (((size_t)b * SEQ + sg1) * NH + h) * DK + d) =
            pkh(oacc[nt][2] * inv1, oacc[nt][3] * inv1);
    }
    (void)dummy;
}

// ---------------- launch ----------------
extern "C" void kernel_launch(void* const* d_in, const int* in_sizes, int n_in,
                              void* d_out, int out_size) {
    const float* x = (const float*)d_in[0];
    const int* tpos = (const int*)d_in[1];
    const float* Wq = (const float*)d_in[2];
    const float* Wk = (const float*)d_in[3];
    const float* Wv = (const float*)d_in[4];
    const float* Wo = (const float*)d_in[5];
    float* out = (float*)d_out;

    unsigned short *gQ, *gK, *gV, *gA, *gX, *gW;
    cudaGetSymbolAddress((void**)&gQ, g_Qh);
    cudaGetSymbolAddress((void**)&gK, g_Kh);
    cudaGetSymbolAddress((void**)&gV, g_Vh);
    cudaGetSymbolAddress((void**)&gA, g_Ah);
    cudaGetSymbolAddress((void**)&gX, g_Xh);
    cudaGetSymbolAddress((void**)&gW, g_Wh);

    cudaFuncSetAttribute(gemm_f16<1>, cudaFuncAttributeMaxDynamicSharedMemorySize,
                         GEMM_SMEM);
    cudaFuncSetAttribute(gemm_f16<0>, cudaFuncAttributeMaxDynamicSharedMemorySize,
                         GEMM_SMEM);
    cudaFuncSetAttribute(attn_f16, cudaFuncAttributeMaxDynamicSharedMemorySize,
                         ATT_SMEM);

    // 1) convert x + all W to fp16
    round_f16_kernel<<<12288, 256>>>(x, Wq, Wk, Wv, Wo);

    // 2) Q/K/V projections (grid.z selects weight/dst); fp16 out
    gemm_f16<1><<<dim3(8, 64, 3), 256, GEMM_SMEM>>>(gX, gW, gQ, gK, gV);

    // 3) RoPE (folds Q-scale)
    const int NPAIR = BATCH * NH * SEQ * (DK / 2);
    rope_kernel<<<dim3((NPAIR + 255) / 256, 2), 256>>>(tpos);

    // 4) attention (fp16, swizzled smem, 5 CTAs/SM)
    attn_f16<<<dim3(SEQ / 64, NH, BATCH), 128, ATT_SMEM>>>(nullptr);

    // 5) output projection (fp32 result)
    gemm_f16<0><<<dim3(8, 64, 1), 256, GEMM_SMEM>>>(gA, gW + (size_t)3 * DM * DM,
                                                    out, out, out);
}

// round 10
// speedup vs baseline: 1.0585x; 1.0585x over previous
#include <cuda_runtime.h>
#include <cuda_fp16.h>
#include <cstdint>

#define BATCH 2
#define SEQ 4096
#define NH 16
#define DK 64
#define DM 1024
#define L2E 1.4426950408889634f

#define QKV_ELEMS ((size_t)BATCH * NH * SEQ * DK)

// ---------------- scratch (no allocation allowed) ----------------
__device__ unsigned short g_Qh[QKV_ELEMS];
__device__ unsigned short g_Kh[QKV_ELEMS];
__device__ unsigned short g_Vh[QKV_ELEMS];
__device__ unsigned short g_Ah[(size_t)BATCH * SEQ * DM];
__device__ unsigned short g_Xh[(size_t)BATCH * SEQ * DM];
__device__ unsigned short g_Wh[(size_t)4 * DM * DM];

// ---------------- helpers ----------------
__device__ __forceinline__ uint32_t pkh(float lo, float hi) {
    uint32_t r;
    asm("cvt.rn.f16x2.f32 %0, %1, %2;" : "=r"(r) : "f"(hi), "f"(lo));
    return r;
}
__device__ __forceinline__ uint32_t h2exp2(uint32_t x) {
    uint32_t r;
    asm("ex2.approx.f16x2 %0, %1;" : "=r"(r) : "r"(x));
    return r;
}
__device__ __forceinline__ uint32_t smem_u32(const void* p) {
    uint32_t a;
    asm("{ .reg .u64 t; cvta.to.shared.u64 t, %1; cvt.u32.u64 %0, t; }"
        : "=r"(a) : "l"(p));
    return a;
}
__device__ __forceinline__ void cp16(uint32_t dst, const void* src) {
    asm volatile("cp.async.cg.shared.global [%0], [%1], 16;" :: "r"(dst), "l"(src));
}
__device__ __forceinline__ void cp_commit() {
    asm volatile("cp.async.commit_group;" ::: "memory");
}
template <int N>
__device__ __forceinline__ void cp_wait() {
    asm volatile("cp.async.wait_group %0;" :: "n"(N) : "memory");
}
__device__ __forceinline__ uint32_t swzb(uint32_t o) {   // 128B-row swizzle
    return o ^ ((o >> 3) & 0x70);
}
__device__ __forceinline__ void ldsm4(uint32_t& r0, uint32_t& r1, uint32_t& r2,
                                      uint32_t& r3, uint32_t a) {
    asm volatile("ldmatrix.sync.aligned.m8n8.x4.shared.b16 {%0,%1,%2,%3}, [%4];"
                 : "=r"(r0), "=r"(r1), "=r"(r2), "=r"(r3) : "r"(a));
}
__device__ __forceinline__ void ldsm4t(uint32_t& r0, uint32_t& r1, uint32_t& r2,
                                       uint32_t& r3, uint32_t a) {
    asm volatile("ldmatrix.sync.aligned.m8n8.x4.trans.shared.b16 {%0,%1,%2,%3}, [%4];"
                 : "=r"(r0), "=r"(r1), "=r"(r2), "=r"(r3) : "r"(a));
}
__device__ __forceinline__ void mma16(float c[4], uint32_t a0, uint32_t a1,
                                      uint32_t a2, uint32_t a3,
                                      uint32_t b0, uint32_t b1) {
    asm volatile(
        "mma.sync.aligned.m16n8k16.row.col.f32.f16.f16.f32 "
        "{%0,%1,%2,%3}, {%4,%5,%6,%7}, {%8,%9}, {%0,%1,%2,%3};"
        : "+f"(c[0]), "+f"(c[1]), "+f"(c[2]), "+f"(c[3])
        : "r"(a0), "r"(a1), "r"(a2), "r"(a3), "r"(b0), "r"(b1));
}

// ---------------- convert x + all W to fp16 ----------------
__global__ __launch_bounds__(256) void round_f16_kernel(
    const float* __restrict__ x, const float* __restrict__ Wq,
    const float* __restrict__ Wk, const float* __restrict__ Wv,
    const float* __restrict__ Wo) {
    size_t i4 = (size_t)blockIdx.x * 256 + threadIdx.x;  // float4 index
    const float4* src;
    uint2* dst;
    if (i4 < 2097152) {
        src = (const float4*)x + i4;
        dst = (uint2*)g_Xh + i4;
    } else {
        size_t r = i4 - 2097152;
        int j = (int)(r >> 18);
        size_t o = r & 262143;
        const float* w = (j == 0) ? Wq : (j == 1) ? Wk : (j == 2) ? Wv : Wo;
        src = (const float4*)w + o;
        dst = (uint2*)g_Wh + (size_t)j * 262144 + o;
    }
    float4 v = *src;
    *dst = make_uint2(pkh(v.x, v.y), pkh(v.z, v.w));
}

// ---------------- fp16 mma GEMM (R8-proven 2-stage) ------------------------
// C = A(Mx1024) * W(1024x1024)^T, tile 128x128, k-block 32, ldmatrix.
#define GSTAGE 20480
#define GEMM_SMEM (2 * GSTAGE)

template <int MODE>
__global__ __launch_bounds__(256, 2) void gemm_f16(
    const unsigned short* __restrict__ Abase,
    const unsigned short* __restrict__ Wbase,
    void* C0, void* C1, void* C2) {
    extern __shared__ __align__(16) char smraw[];
    const uint32_t smb = smem_u32(smraw);

    const int tid = threadIdx.x, wid = tid >> 5, lane = tid & 31;
    const int g = lane >> 2, tig = lane & 3;
    const int wm = (wid & 1) * 64, wn = (wid >> 1) * 32;
    const int z = blockIdx.z;
    const int m0 = blockIdx.y * 128, n0 = blockIdx.x * 128;
    const unsigned short* W = Wbase + (size_t)z * (DM * DM);
    void* C = (z == 0) ? C0 : (z == 1) ? C1 : C2;

    float acc[4][4][4];
#pragma unroll
    for (int mt = 0; mt < 4; mt++)
#pragma unroll
        for (int nt = 0; nt < 4; nt++)
#pragma unroll
            for (int k = 0; k < 4; k++) acc[mt][nt][k] = 0.f;

    const int a_r = (lane & 7) + ((lane >> 3) & 1) * 8;
    const int a_c = (lane >> 4) << 3;
    const int lr2 = tid >> 2, lc2 = (tid & 3) * 8;

    auto fill = [&](int s) {
        const uint32_t st = smb + (uint32_t)(s & 1) * GSTAGE;
        const int kb = s * 32;
#pragma unroll
        for (int i = 0; i < 2; i++) {
            int r = lr2 + i * 64;
            cp16(st + r * 80 + (lc2 >> 3) * 16,
                 Abase + (size_t)(m0 + r) * DM + kb + lc2);
        }
#pragma unroll
        for (int i = 0; i < 2; i++) {
            int r = lr2 + i * 64;
            cp16(st + 10240 + r * 80 + (lc2 >> 3) * 16,
                 W + (size_t)(n0 + r) * DM + kb + lc2);
        }
        cp_commit();
    };

    fill(0);

    for (int s = 0; s < 32; s++) {
        if (s + 1 < 32) {
            fill(s + 1);
            cp_wait<1>();
        } else {
            cp_wait<0>();
        }
        __syncthreads();
        const uint32_t asb = smb + (uint32_t)(s & 1) * GSTAGE;
        const uint32_t wsb = asb + 10240;

#pragma unroll
        for (int kk = 0; kk < 32; kk += 16) {
            uint32_t a[4][4], b[2][4];
#pragma unroll
            for (int mt = 0; mt < 4; mt++) {
                int ar = wm + mt * 16 + a_r;
                ldsm4(a[mt][0], a[mt][1], a[mt][2], a[mt][3],
                      asb + (uint32_t)(ar * 40 + kk + a_c) * 2);
            }
#pragma unroll
            for (int j = 0; j < 2; j++) {
                int nr = wn + j * 16 + (lane & 7) + ((lane >> 4) << 3);
                int kc = kk + ((lane >> 3) & 1) * 8;
                ldsm4(b[j][0], b[j][1], b[j][2], b[j][3],
                      wsb + (uint32_t)(nr * 40 + kc) * 2);
            }
#pragma unroll
            for (int mt = 0; mt < 4; mt++)
#pragma unroll
                for (int j = 0; j < 2; j++) {
                    mma16(acc[mt][2 * j], a[mt][0], a[mt][1], a[mt][2], a[mt][3],
                          b[j][0], b[j][1]);
                    mma16(acc[mt][2 * j + 1], a[mt][0], a[mt][1], a[mt][2], a[mt][3],
                          b[j][2], b[j][3]);
                }
        }
        __syncthreads();
    }

#pragma unroll
    for (int mt = 0; mt < 4; mt++) {
#pragma unroll
        for (int nt = 0; nt < 4; nt++) {
            int r0 = m0 + wm + mt * 16 + g;
            int r1 = r0 + 8;
            int cc = n0 + wn + nt * 8 + 2 * tig;
            if (MODE == 0) {
                float* Cf = (float*)C;
                *(float2*)&Cf[(size_t)r0 * DM + cc] =
                    make_float2(acc[mt][nt][0], acc[mt][nt][1]);
                *(float2*)&Cf[(size_t)r1 * DM + cc] =
                    make_float2(acc[mt][nt][2], acc[mt][nt][3]);
            } else {
                unsigned short* Ch = (unsigned short*)C;
                int h = cc >> 6, d = cc & 63;
                int b0i = r0 >> 12, s0 = r0 & (SEQ - 1);
                int b1i = r1 >> 12, s1 = r1 & (SEQ - 1);
                *(uint32_t*)(Ch + ((size_t)(b0i * NH + h) * SEQ + s0) * DK + d) =
                    pkh(acc[mt][nt][0], acc[mt][nt][1]);
                *(uint32_t*)(Ch + ((size_t)(b1i * NH + h) * SEQ + s1) * DK + d) =
                    pkh(acc[mt][nt][2], acc[mt][nt][3]);
            }
        }
    }
}

// ---------------- RoPE (fp16 in-place; folds Q-scale) ----------------
__global__ void rope_kernel(const int* __restrict__ pos) {
    const int NPAIR = BATCH * NH * SEQ * (DK / 2);
    int i = blockIdx.x * blockDim.x + threadIdx.x;
    if (i >= NPAIR) return;
    int j = i & 31;
    int s = (i >> 5) & (SEQ - 1);
    int h = (i >> 17) & (NH - 1);
    int b = i >> 21;

    const bool isQ = (blockIdx.y == 0);
    uint32_t* ptr32 = (uint32_t*)(isQ ? g_Qh : g_Kh);
    int p = pos[b * SEQ + s];
    float freq = exp2f(-(float)j * (13.287712379549449f / 32.f));
    float ang = (float)p * freq;
    float sn, cs;
    sincosf(ang, &sn, &cs);

    size_t idx = ((size_t)(b * NH + h) * SEQ + s) * 32 + j;
    uint32_t pv = ptr32[idx];
    __half2 hv = *(__half2*)&pv;
    float e = __half2float(__low2half(hv));
    float o = __half2float(__high2half(hv));
    float ne = e * cs - o * sn;
    float no = e * sn + o * cs;
    if (isQ) {
        const float qscale = 0.125f * L2E;
        ne *= qscale;
        no *= qscale;
    }
    ptr32[idx] = pkh(ne, no);
}

// ---------------- causal flash attention, fp16, h2exp2 + ones-mma rowsum ---
// Br=Bc=64, 128 threads (4 warps x 16 rows). Q frags in registers.
// smem: 5 tiles x 8192B (Q | K0 K1 | V0 V1), 128B swizzled rows -> 40960 B.
#define AT_K 8192
#define AT_V 24576
#define ATT_SMEM 40960

__global__ __launch_bounds__(128, 5) void attn_f16(float* dummy) {
    extern __shared__ __align__(16) char asm_raw[];
    const uint32_t smb = smem_u32(asm_raw);

    const int qt = 63 - (int)blockIdx.x;
    const int h = blockIdx.y;
    const int b = blockIdx.z;
    const int tid = threadIdx.x;
    const int wid = tid >> 5, lane = tid & 31;
    const int g = lane >> 2, tig = lane & 3;
    const int wr = wid * 16;

    const size_t bh = (size_t)(b * NH + h) * SEQ;
    const unsigned short* Qb = g_Qh + (bh + (size_t)qt * 64) * DK;
    const unsigned short* Kb = g_Kh + bh * DK;
    const unsigned short* Vb = g_Vh + bh * DK;

    const int l_r = (lane & 7) + ((lane >> 3) & 1) * 8;
    const int l_c8 = (lane >> 4) << 3;

    auto prefetch = [&](int kt, int buf) {
        const uint32_t kst = smb + AT_K + buf * 8192;
        const uint32_t vst = smb + AT_V + buf * 8192;
#pragma unroll
        for (int i = 0; i < 4; i++) {
            int q = tid + i * 128;
            int r = q >> 3, c = q & 7;
            cp16(kst + swzb(r * 128 + c * 16),
                 Kb + (size_t)(kt * 64 + r) * DK + c * 8);
        }
#pragma unroll
        for (int i = 0; i < 4; i++) {
            int q = tid + i * 128;
            int r = q >> 3, c = q & 7;
            cp16(vst + swzb(r * 128 + c * 16),
                 Vb + (size_t)(kt * 64 + r) * DK + c * 8);
        }
        cp_commit();
    };

    // Q tile -> swizzled smem (once)
#pragma unroll
    for (int p = 0; p < 4; p++) {
        int idx = p * 128 + tid;
        int r = idx >> 3, c = idx & 7;
        *(uint4*)(asm_raw + swzb(r * 128 + c * 16)) =
            *(const uint4*)(Qb + (size_t)r * DK + c * 8);
    }
    prefetch(0, 0);
    __syncthreads();

    // hoist Q fragments (4 k-chunks of 16)
    uint32_t qf[4][4];
#pragma unroll
    for (int kq = 0; kq < 4; kq++) {
        int qr = wr + l_r;
        int qcb = (kq * 16 + l_c8) * 2;
        ldsm4(qf[kq][0], qf[kq][1], qf[kq][2], qf[kq][3],
              smb + swzb((uint32_t)(qr * 128 + qcb)));
    }

    float oacc[8][4];
    float lacc[4] = {0.f, 0.f, 0.f, 0.f};   // rowsum accumulators via ones-mma
    float m0 = -1e30f, m1 = -1e30f;
#pragma unroll
    for (int nt = 0; nt < 8; nt++)
#pragma unroll
        for (int k = 0; k < 4; k++) oacc[nt][k] = 0.f;

    const uint32_t ONESH = 0x3C003C00u;      // {1.0h, 1.0h}

    const int ntiles = qt + 1;
    for (int kt = 0; kt < ntiles; kt++) {
        const int buf = kt & 1;
        __syncthreads();
        if (kt + 1 < ntiles) {
            prefetch(kt + 1, buf ^ 1);
            cp_wait<1>();
        } else {
            cp_wait<0>();
        }
        __syncthreads();

        const uint32_t ksb = smb + AT_K + buf * 8192;
        const uint32_t vsb = smb + AT_V + buf * 8192;

        // S = Q K^T
        float sacc[8][4];
#pragma unroll
        for (int nt = 0; nt < 8; nt++)
#pragma unroll
            for (int k = 0; k < 4; k++) sacc[nt][k] = 0.f;

#pragma unroll
        for (int kq = 0; kq < 4; kq++) {
            const int kk = kq * 16;
#pragma unroll
            for (int j = 0; j < 4; j++) {
                int nr = j * 16 + (lane & 7) + l_c8;
                int kcb = (kk + ((lane >> 3) & 1) * 8) * 2;
                uint32_t b0, b1, b2, b3;
                ldsm4(b0, b1, b2, b3, ksb + swzb((uint32_t)(nr * 128 + kcb)));
                mma16(sacc[2 * j], qf[kq][0], qf[kq][1], qf[kq][2], qf[kq][3], b0, b1);
                mma16(sacc[2 * j + 1], qf[kq][0], qf[kq][1], qf[kq][2], qf[kq][3], b2, b3);
            }
        }

        if (kt == qt) {  // causal mask on diagonal tile
#pragma unroll
            for (int nt = 0; nt < 8; nt++) {
                int c0 = nt * 8 + 2 * tig, c1 = c0 + 1;
                if (c0 > wr + g) sacc[nt][0] = -1e30f;
                if (c1 > wr + g) sacc[nt][1] = -1e30f;
                if (c0 > wr + g + 8) sacc[nt][2] = -1e30f;
                if (c1 > wr + g + 8) sacc[nt][3] = -1e30f;
            }
        }

        // online softmax: row-max (quad shuffles), then P in fp16 via h2exp2
        float tm0 = -1e30f, tm1 = -1e30f;
#pragma unroll
        for (int nt = 0; nt < 8; nt++) {
            tm0 = fmaxf(tm0, fmaxf(sacc[nt][0], sacc[nt][1]));
            tm1 = fmaxf(tm1, fmaxf(sacc[nt][2], sacc[nt][3]));
        }
        tm0 = fmaxf(tm0, __shfl_xor_sync(0xffffffffu, tm0, 1));
        tm0 = fmaxf(tm0, __shfl_xor_sync(0xffffffffu, tm0, 2));
        tm1 = fmaxf(tm1, __shfl_xor_sync(0xffffffffu, tm1, 1));
        tm1 = fmaxf(tm1, __shfl_xor_sync(0xffffffffu, tm1, 2));

        float mn0 = fmaxf(m0, tm0), mn1 = fmaxf(m1, tm1);
        float al0 = exp2f(m0 - mn0), al1 = exp2f(m1 - mn1);
        m0 = mn0; m1 = mn1;

        uint32_t ph[8][2];
#pragma unroll
        for (int nt = 0; nt < 8; nt++) {
            ph[nt][0] = h2exp2(pkh(sacc[nt][0] - mn0, sacc[nt][1] - mn0));
            ph[nt][1] = h2exp2(pkh(sacc[nt][2] - mn1, sacc[nt][3] - mn1));
        }

        // rescale running accumulators
        lacc[0] *= al0; lacc[1] *= al0; lacc[2] *= al1; lacc[3] *= al1;
#pragma unroll
        for (int nt = 0; nt < 8; nt++) {
            oacc[nt][0] *= al0; oacc[nt][1] *= al0;
            oacc[nt][2] *= al1; oacc[nt][3] *= al1;
        }

        // O += P V, and rowsum += P @ ones (tensor pipe, no shuffles)
#pragma unroll
        for (int kc = 0; kc < 64; kc += 16) {
            const int e = kc >> 3;
            uint32_t a0 = ph[e][0];
            uint32_t a1 = ph[e][1];
            uint32_t a2 = ph[e + 1][0];
            uint32_t a3 = ph[e + 1][1];
            mma16(lacc, a0, a1, a2, a3, ONESH, ONESH);
#pragma unroll
            for (int j = 0; j < 4; j++) {
                int vr = kc + l_r;
                int vcb = (j * 16 + l_c8) * 2;
                uint32_t b0, b1, b2, b3;
                ldsm4t(b0, b1, b2, b3, vsb + swzb((uint32_t)(vr * 128 + vcb)));
                mma16(oacc[2 * j], a0, a1, a2, a3, b0, b1);
                mma16(oacc[2 * j + 1], a0, a1, a2, a3, b2, b3);
            }
        }
    }

    // normalize + fp16 write [b][s][h][d] (feeds Wo GEMM)
    float inv0 = 1.f / lacc[0], inv1 = 1.f / lacc[2];
    int sg0 = qt * 64 + wr + g, sg1 = sg0 + 8;
#pragma unroll
    for (int nt = 0; nt < 8; nt++) {
        int d = nt * 8 + 2 * tig;
        *(uint32_t*)(g_Ah + (((size_t)b * SEQ + sg0) * NH + h) * DK + d) =
            pkh(oacc[nt][0] * inv0, oacc[nt][1] * inv0);
        *(uint32_t*)(g_Ah + (((size_t)b * SEQ + sg1) * NH + h) * DK + d) =
            pkh(oacc[nt][2] * inv1, oacc[nt][3] * inv1);
    }
    (void)dummy;
}

// ---------------- launch ----------------
extern "C" void kernel_launch(void* const* d_in, const int* in_sizes, int n_in,
                              void* d_out, int out_size) {
    const float* x = (const float*)d_in[0];
    const int* tpos = (const int*)d_in[1];
    const float* Wq = (const float*)d_in[2];
    const float* Wk = (const float*)d_in[3];
    const float* Wv = (const float*)d_in[4];
    const float* Wo = (const float*)d_in[5];
    float* out = (float*)d_out;

    unsigned short *gQ, *gK, *gV, *gA, *gX, *gW;
    cudaGetSymbolAddress((void**)&gQ, g_Qh);
    cudaGetSymbolAddress((void**)&gK, g_Kh);
    cudaGetSymbolAddress((void**)&gV, g_Vh);
    cudaGetSymbolAddress((void**)&gA, g_Ah);
    cudaGetSymbolAddress((void**)&gX, g_Xh);
    cudaGetSymbolAddress((void**)&gW, g_Wh);

    cudaFuncSetAttribute(gemm_f16<1>, cudaFuncAttributeMaxDynamicSharedMemorySize,
                         GEMM_SMEM);
    cudaFuncSetAttribute(gemm_f16<0>, cudaFuncAttributeMaxDynamicSharedMemorySize,
                         GEMM_SMEM);
    cudaFuncSetAttribute(attn_f16, cudaFuncAttributeMaxDynamicSharedMemorySize,
                         ATT_SMEM);

    // 1) convert x + all W to fp16
    round_f16_kernel<<<12288, 256>>>(x, Wq, Wk, Wv, Wo);

    // 2) Q/K/V projections (grid.z selects weight/dst); fp16 out
    gemm_f16<1><<<dim3(8, 64, 3), 256, GEMM_SMEM>>>(gX, gW, gQ, gK, gV);

    // 3) RoPE (folds Q-scale)
    const int NPAIR = BATCH * NH * SEQ * (DK / 2);
    rope_kernel<<<dim3((NPAIR + 255) / 256, 2), 256>>>(tpos);

    // 4) attention (fp16, swizzled smem, h2exp2 + ones-mma rowsum)
    attn_f16<<<dim3(SEQ / 64, NH, BATCH), 128, ATT_SMEM>>>(nullptr);

    // 5) output projection (fp32 result)
    gemm_f16<0><<<dim3(8, 64, 1), 256, GEMM_SMEM>>>(gA, gW + (size_t)3 * DM * DM,
                                                    out, out, out);
}

// round 11
// speedup vs baseline: 1.1908x; 1.1250x over previous
#include <cuda_runtime.h>
#include <cuda_fp16.h>
#include <cstdint>

#define BATCH 2
#define SEQ 4096
#define NH 16
#define DK 64
#define DM 1024
#define L2E 1.4426950408889634f

#define QKV_ELEMS ((size_t)BATCH * NH * SEQ * DK)

// ---------------- scratch (no allocation allowed) ----------------
__device__ unsigned short g_Qh[QKV_ELEMS];
__device__ unsigned short g_Kh[QKV_ELEMS];
__device__ unsigned short g_Vh[QKV_ELEMS];
__device__ unsigned short g_Ah[(size_t)BATCH * SEQ * DM];
__device__ unsigned short g_Xh[(size_t)BATCH * SEQ * DM];
__device__ unsigned short g_Wh[(size_t)4 * DM * DM];

// ---------------- helpers ----------------
__device__ __forceinline__ uint32_t pkh(float lo, float hi) {
    uint32_t r;
    asm("cvt.rn.f16x2.f32 %0, %1, %2;" : "=r"(r) : "f"(hi), "f"(lo));
    return r;
}
__device__ __forceinline__ uint32_t h2exp2(uint32_t x) {
    uint32_t r;
    asm("ex2.approx.f16x2 %0, %1;" : "=r"(r) : "r"(x));
    return r;
}
__device__ __forceinline__ uint32_t smem_u32(const void* p) {
    uint32_t a;
    asm("{ .reg .u64 t; cvta.to.shared.u64 t, %1; cvt.u32.u64 %0, t; }"
        : "=r"(a) : "l"(p));
    return a;
}
__device__ __forceinline__ void cp16(uint32_t dst, const void* src) {
    asm volatile("cp.async.cg.shared.global [%0], [%1], 16;" :: "r"(dst), "l"(src));
}
__device__ __forceinline__ void cp_commit() {
    asm volatile("cp.async.commit_group;" ::: "memory");
}
template <int N>
__device__ __forceinline__ void cp_wait() {
    asm volatile("cp.async.wait_group %0;" :: "n"(N) : "memory");
}
__device__ __forceinline__ uint32_t swzb(uint32_t o) {   // 128B-row swizzle
    return o ^ ((o >> 3) & 0x70);
}
__device__ __forceinline__ void ldsm4(uint32_t& r0, uint32_t& r1, uint32_t& r2,
                                      uint32_t& r3, uint32_t a) {
    asm volatile("ldmatrix.sync.aligned.m8n8.x4.shared.b16 {%0,%1,%2,%3}, [%4];"
                 : "=r"(r0), "=r"(r1), "=r"(r2), "=r"(r3) : "r"(a));
}
__device__ __forceinline__ void ldsm4t(uint32_t& r0, uint32_t& r1, uint32_t& r2,
                                       uint32_t& r3, uint32_t a) {
    asm volatile("ldmatrix.sync.aligned.m8n8.x4.trans.shared.b16 {%0,%1,%2,%3}, [%4];"
                 : "=r"(r0), "=r"(r1), "=r"(r2), "=r"(r3) : "r"(a));
}
__device__ __forceinline__ void mma16(float c[4], uint32_t a0, uint32_t a1,
                                      uint32_t a2, uint32_t a3,
                                      uint32_t b0, uint32_t b1) {
    asm volatile(
        "mma.sync.aligned.m16n8k16.row.col.f32.f16.f16.f32 "
        "{%0,%1,%2,%3}, {%4,%5,%6,%7}, {%8,%9}, {%0,%1,%2,%3};"
        : "+f"(c[0]), "+f"(c[1]), "+f"(c[2]), "+f"(c[3])
        : "r"(a0), "r"(a1), "r"(a2), "r"(a3), "r"(b0), "r"(b1));
}

// ---------------- convert x + all W to fp16 ----------------
__global__ __launch_bounds__(256) void round_f16_kernel(
    const float* __restrict__ x, const float* __restrict__ Wq,
    const float* __restrict__ Wk, const float* __restrict__ Wv,
    const float* __restrict__ Wo) {
    size_t i4 = (size_t)blockIdx.x * 256 + threadIdx.x;  // float4 index
    const float4* src;
    uint2* dst;
    if (i4 < 2097152) {
        src = (const float4*)x + i4;
        dst = (uint2*)g_Xh + i4;
    } else {
        size_t r = i4 - 2097152;
        int j = (int)(r >> 18);
        size_t o = r & 262143;
        const float* w = (j == 0) ? Wq : (j == 1) ? Wk : (j == 2) ? Wv : Wo;
        src = (const float4*)w + o;
        dst = (uint2*)g_Wh + (size_t)j * 262144 + o;
    }
    float4 v = *src;
    *dst = make_uint2(pkh(v.x, v.y), pkh(v.z, v.w));
}

// ---------------- fp16 mma GEMM: k-block 64, swizzled 128B rows ------------
// C = A(Mx1024) * W(1024x1024)^T, tile 128x128, 2-stage cp.async, ldmatrix.
// smem/stage: A 128x64h (16KB) + W 128x64h (16KB) = 32KB; 2 stages = 64KB.
#define GSTAGE 32768
#define GEMM_SMEM (2 * GSTAGE)

template <int MODE>
__global__ __launch_bounds__(256, 2) void gemm_f16(
    const unsigned short* __restrict__ Abase,
    const unsigned short* __restrict__ Wbase,
    void* C0, void* C1, void* C2) {
    extern __shared__ __align__(16) char smraw[];
    const uint32_t smb = smem_u32(smraw);

    const int tid = threadIdx.x, wid = tid >> 5, lane = tid & 31;
    const int g = lane >> 2, tig = lane & 3;
    const int wm = (wid & 1) * 64, wn = (wid >> 1) * 32;
    const int z = blockIdx.z;
    const int m0 = blockIdx.y * 128, n0 = blockIdx.x * 128;
    const unsigned short* W = Wbase + (size_t)z * (DM * DM);
    void* C = (z == 0) ? C0 : (z == 1) ? C1 : C2;

    float acc[4][4][4];
#pragma unroll
    for (int mt = 0; mt < 4; mt++)
#pragma unroll
        for (int nt = 0; nt < 4; nt++)
#pragma unroll
            for (int k = 0; k < 4; k++) acc[mt][nt][k] = 0.f;

    const int a_r = (lane & 7) + ((lane >> 3) & 1) * 8;
    const int a_c = (lane >> 4) << 3;
    const int lr8 = tid >> 3, lc8 = (tid & 7);   // row 0..31(x4), col-chunk 0..7

    auto fill = [&](int s) {
        const uint32_t st = smb + (uint32_t)(s & 1) * GSTAGE;
        const int kb = s * 64;
#pragma unroll
        for (int i = 0; i < 4; i++) {           // A: 1024 chunks of 16B
            int r = lr8 + i * 32;
            cp16(st + swzb(r * 128 + lc8 * 16),
                 Abase + (size_t)(m0 + r) * DM + kb + lc8 * 8);
        }
#pragma unroll
        for (int i = 0; i < 4; i++) {           // W: 1024 chunks of 16B
            int r = lr8 + i * 32;
            cp16(st + 16384 + swzb(r * 128 + lc8 * 16),
                 W + (size_t)(n0 + r) * DM + kb + lc8 * 8);
        }
        cp_commit();
    };

    fill(0);

    for (int s = 0; s < 16; s++) {
        if (s + 1 < 16) {
            fill(s + 1);
            cp_wait<1>();
        } else {
            cp_wait<0>();
        }
        __syncthreads();
        const uint32_t asb = smb + (uint32_t)(s & 1) * GSTAGE;
        const uint32_t wsb = asb + 16384;

#pragma unroll
        for (int kk = 0; kk < 64; kk += 16) {
            uint32_t a[4][4], b[2][4];
#pragma unroll
            for (int mt = 0; mt < 4; mt++) {
                int ar = wm + mt * 16 + a_r;
                ldsm4(a[mt][0], a[mt][1], a[mt][2], a[mt][3],
                      asb + swzb((uint32_t)(ar * 128 + (kk + a_c) * 2)));
            }
#pragma unroll
            for (int j = 0; j < 2; j++) {
                int nr = wn + j * 16 + (lane & 7) + ((lane >> 4) << 3);
                int kc = kk + ((lane >> 3) & 1) * 8;
                ldsm4(b[j][0], b[j][1], b[j][2], b[j][3],
                      wsb + swzb((uint32_t)(nr * 128 + kc * 2)));
            }
#pragma unroll
            for (int mt = 0; mt < 4; mt++)
#pragma unroll
                for (int j = 0; j < 2; j++) {
                    mma16(acc[mt][2 * j], a[mt][0], a[mt][1], a[mt][2], a[mt][3],
                          b[j][0], b[j][1]);
                    mma16(acc[mt][2 * j + 1], a[mt][0], a[mt][1], a[mt][2], a[mt][3],
                          b[j][2], b[j][3]);
                }
        }
        __syncthreads();
    }

#pragma unroll
    for (int mt = 0; mt < 4; mt++) {
#pragma unroll
        for (int nt = 0; nt < 4; nt++) {
            int r0 = m0 + wm + mt * 16 + g;
            int r1 = r0 + 8;
            int cc = n0 + wn + nt * 8 + 2 * tig;
            if (MODE == 0) {
                float* Cf = (float*)C;
                *(float2*)&Cf[(size_t)r0 * DM + cc] =
                    make_float2(acc[mt][nt][0], acc[mt][nt][1]);
                *(float2*)&Cf[(size_t)r1 * DM + cc] =
                    make_float2(acc[mt][nt][2], acc[mt][nt][3]);
            } else {
                unsigned short* Ch = (unsigned short*)C;
                int h = cc >> 6, d = cc & 63;
                int b0i = r0 >> 12, s0 = r0 & (SEQ - 1);
                int b1i = r1 >> 12, s1 = r1 & (SEQ - 1);
                *(uint32_t*)(Ch + ((size_t)(b0i * NH + h) * SEQ + s0) * DK + d) =
                    pkh(acc[mt][nt][0], acc[mt][nt][1]);
                *(uint32_t*)(Ch + ((size_t)(b1i * NH + h) * SEQ + s1) * DK + d) =
                    pkh(acc[mt][nt][2], acc[mt][nt][3]);
            }
        }
    }
}

// ---------------- RoPE (fp16 in-place; folds Q-scale) ----------------
__global__ void rope_kernel(const int* __restrict__ pos) {
    const int NPAIR = BATCH * NH * SEQ * (DK / 2);
    int i = blockIdx.x * blockDim.x + threadIdx.x;
    if (i >= NPAIR) return;
    int j = i & 31;
    int s = (i >> 5) & (SEQ - 1);
    int h = (i >> 17) & (NH - 1);
    int b = i >> 21;

    const bool isQ = (blockIdx.y == 0);
    uint32_t* ptr32 = (uint32_t*)(isQ ? g_Qh : g_Kh);
    int p = pos[b * SEQ + s];
    float freq = exp2f(-(float)j * (13.287712379549449f / 32.f));
    float ang = (float)p * freq;
    float sn, cs;
    sincosf(ang, &sn, &cs);

    size_t idx = ((size_t)(b * NH + h) * SEQ + s) * 32 + j;
    uint32_t pv = ptr32[idx];
    __half2 hv = *(__half2*)&pv;
    float e = __half2float(__low2half(hv));
    float o = __half2float(__high2half(hv));
    float ne = e * cs - o * sn;
    float no = e * sn + o * cs;
    if (isQ) {
        const float qscale = 0.125f * L2E;
        ne *= qscale;
        no *= qscale;
    }
    ptr32[idx] = pkh(ne, no);
}

// ---------------- causal flash attention (R10-proven, unchanged) -----------
// Br=Bc=64, 128 threads (4 warps x 16 rows). Q frags in registers.
// smem: 5 tiles x 8192B (Q | K0 K1 | V0 V1), 128B swizzled rows -> 40960 B.
#define AT_K 8192
#define AT_V 24576
#define ATT_SMEM 40960

__global__ __launch_bounds__(128, 5) void attn_f16(float* dummy) {
    extern __shared__ __align__(16) char asm_raw[];
    const uint32_t smb = smem_u32(asm_raw);

    const int qt = 63 - (int)blockIdx.x;
    const int h = blockIdx.y;
    const int b = blockIdx.z;
    const int tid = threadIdx.x;
    const int wid = tid >> 5, lane = tid & 31;
    const int g = lane >> 2, tig = lane & 3;
    const int wr = wid * 16;

    const size_t bh = (size_t)(b * NH + h) * SEQ;
    const unsigned short* Qb = g_Qh + (bh + (size_t)qt * 64) * DK;
    const unsigned short* Kb = g_Kh + bh * DK;
    const unsigned short* Vb = g_Vh + bh * DK;

    const int l_r = (lane & 7) + ((lane >> 3) & 1) * 8;
    const int l_c8 = (lane >> 4) << 3;

    auto prefetch = [&](int kt, int buf) {
        const uint32_t kst = smb + AT_K + buf * 8192;
        const uint32_t vst = smb + AT_V + buf * 8192;
#pragma unroll
        for (int i = 0; i < 4; i++) {
            int q = tid + i * 128;
            int r = q >> 3, c = q & 7;
            cp16(kst + swzb(r * 128 + c * 16),
                 Kb + (size_t)(kt * 64 + r) * DK + c * 8);
        }
#pragma unroll
        for (int i = 0; i < 4; i++) {
            int q = tid + i * 128;
            int r = q >> 3, c = q & 7;
            cp16(vst + swzb(r * 128 + c * 16),
                 Vb + (size_t)(kt * 64 + r) * DK + c * 8);
        }
        cp_commit();
    };

    // Q tile -> swizzled smem (once)
#pragma unroll
    for (int p = 0; p < 4; p++) {
        int idx = p * 128 + tid;
        int r = idx >> 3, c = idx & 7;
        *(uint4*)(asm_raw + swzb(r * 128 + c * 16)) =
            *(const uint4*)(Qb + (size_t)r * DK + c * 8);
    }
    prefetch(0, 0);
    __syncthreads();

    // hoist Q fragments (4 k-chunks of 16)
    uint32_t qf[4][4];
#pragma unroll
    for (int kq = 0; kq < 4; kq++) {
        int qr = wr + l_r;
        int qcb = (kq * 16 + l_c8) * 2;
        ldsm4(qf[kq][0], qf[kq][1], qf[kq][2], qf[kq][3],
              smb + swzb((uint32_t)(qr * 128 + qcb)));
    }

    float oacc[8][4];
    float lacc[4] = {0.f, 0.f, 0.f, 0.f};   // rowsum accumulators via ones-mma
    float m0 = -1e30f, m1 = -1e30f;
#pragma unroll
    for (int nt = 0; nt < 8; nt++)
#pragma unroll
        for (int k = 0; k < 4; k++) oacc[nt][k] = 0.f;

    const uint32_t ONESH = 0x3C003C00u;      // {1.0h, 1.0h}

    const int ntiles = qt + 1;
    for (int kt = 0; kt < ntiles; kt++) {
        const int buf = kt & 1;
        __syncthreads();
        if (kt + 1 < ntiles) {
            prefetch(kt + 1, buf ^ 1);
            cp_wait<1>();
        } else {
            cp_wait<0>();
        }
        __syncthreads();

        const uint32_t ksb = smb + AT_K + buf * 8192;
        const uint32_t vsb = smb + AT_V + buf * 8192;

        // S = Q K^T
        float sacc[8][4];
#pragma unroll
        for (int nt = 0; nt < 8; nt++)
#pragma unroll
            for (int k = 0; k < 4; k++) sacc[nt][k] = 0.f;

#pragma unroll
        for (int kq = 0; kq < 4; kq++) {
            const int kk = kq * 16;
#pragma unroll
            for (int j = 0; j < 4; j++) {
                int nr = j * 16 + (lane & 7) + l_c8;
                int kcb = (kk + ((lane >> 3) & 1) * 8) * 2;
                uint32_t b0, b1, b2, b3;
                ldsm4(b0, b1, b2, b3, ksb + swzb((uint32_t)(nr * 128 + kcb)));
                mma16(sacc[2 * j], qf[kq][0], qf[kq][1], qf[kq][2], qf[kq][3], b0, b1);
                mma16(sacc[2 * j + 1], qf[kq][0], qf[kq][1], qf[kq][2], qf[kq][3], b2, b3);
            }
        }

        if (kt == qt) {  // causal mask on diagonal tile
#pragma unroll
            for (int nt = 0; nt < 8; nt++) {
                int c0 = nt * 8 + 2 * tig, c1 = c0 + 1;
                if (c0 > wr + g) sacc[nt][0] = -1e30f;
                if (c1 > wr + g) sacc[nt][1] = -1e30f;
                if (c0 > wr + g + 8) sacc[nt][2] = -1e30f;
                if (c1 > wr + g + 8) sacc[nt][3] = -1e30f;
            }
        }

        // online softmax: row-max (quad shuffles), then P in fp16 via h2exp2
        float tm0 = -1e30f, tm1 = -1e30f;
#pragma unroll
        for (int nt = 0; nt < 8; nt++) {
            tm0 = fmaxf(tm0, fmaxf(sacc[nt][0], sacc[nt][1]));
            tm1 = fmaxf(tm1, fmaxf(sacc[nt][2], sacc[nt][3]));
        }
        tm0 = fmaxf(tm0, __shfl_xor_sync(0xffffffffu, tm0, 1));
        tm0 = fmaxf(tm0, __shfl_xor_sync(0xffffffffu, tm0, 2));
        tm1 = fmaxf(tm1, __shfl_xor_sync(0xffffffffu, tm1, 1));
        tm1 = fmaxf(tm1, __shfl_xor_sync(0xffffffffu, tm1, 2));

        float mn0 = fmaxf(m0, tm0), mn1 = fmaxf(m1, tm1);
        float al0 = exp2f(m0 - mn0), al1 = exp2f(m1 - mn1);
        m0 = mn0; m1 = mn1;

        uint32_t ph[8][2];
#pragma unroll
        for (int nt = 0; nt < 8; nt++) {
            ph[nt][0] = h2exp2(pkh(sacc[nt][0] - mn0, sacc[nt][1] - mn0));
            ph[nt][1] = h2exp2(pkh(sacc[nt][2] - mn1, sacc[nt][3] - mn1));
        }

        // rescale running accumulators
        lacc[0] *= al0; lacc[1] *= al0; lacc[2] *= al1; lacc[3] *= al1;
#pragma unroll
        for (int nt = 0; nt < 8; nt++) {
            oacc[nt][0] *= al0; oacc[nt][1] *= al0;
            oacc[nt][2] *= al1; oacc[nt][3] *= al1;
        }

        // O += P V, and rowsum += P @ ones (tensor pipe, no shuffles)
#pragma unroll
        for (int kc = 0; kc < 64; kc += 16) {
            const int e = kc >> 3;
            uint32_t a0 = ph[e][0];
            uint32_t a1 = ph[e][1];
            uint32_t a2 = ph[e + 1][0];
            uint32_t a3 = ph[e + 1][1];
            mma16(lacc, a0, a1, a2, a3, ONESH, ONESH);
#pragma unroll
            for (int j = 0; j < 4; j++) {
                int vr = kc + l_r;
                int vcb = (j * 16 + l_c8) * 2;
                uint32_t b0, b1, b2, b3;
                ldsm4t(b0, b1, b2, b3, vsb + swzb((uint32_t)(vr * 128 + vcb)));
                mma16(oacc[2 * j], a0, a1, a2, a3, b0, b1);
                mma16(oacc[2 * j + 1], a0, a1, a2, a3, b2, b3);
            }
        }
    }

    // normalize + fp16 write [b][s][h][d] (feeds Wo GEMM)
    float inv0 = 1.f / lacc[0], inv1 = 1.f / lacc[2];
    int sg0 = qt * 64 + wr + g, sg1 = sg0 + 8;
#pragma unroll
    for (int nt = 0; nt < 8; nt++) {
        int d = nt * 8 + 2 * tig;
        *(uint32_t*)(g_Ah + (((size_t)b * SEQ + sg0) * NH + h) * DK + d) =
            pkh(oacc[nt][0] * inv0, oacc[nt][1] * inv0);
        *(uint32_t*)(g_Ah + (((size_t)b * SEQ + sg1) * NH + h) * DK + d) =
            pkh(oacc[nt][2] * inv1, oacc[nt][3] * inv1);
    }
    (void)dummy;
}

// ---------------- launch ----------------
extern "C" void kernel_launch(void* const* d_in, const int* in_sizes, int n_in,
                              void* d_out, int out_size) {
    const float* x = (const float*)d_in[0];
    const int* tpos = (const int*)d_in[1];
    const float* Wq = (const float*)d_in[2];
    const float* Wk = (const float*)d_in[3];
    const float* Wv = (const float*)d_in[4];
    const float* Wo = (const float*)d_in[5];
    float* out = (float*)d_out;

    unsigned short *gQ, *gK, *gV, *gA, *gX, *gW;
    cudaGetSymbolAddress((void**)&gQ, g_Qh);
    cudaGetSymbolAddress((void**)&gK, g_Kh);
    cudaGetSymbolAddress((void**)&gV, g_Vh);
    cudaGetSymbolAddress((void**)&gA, g_Ah);
    cudaGetSymbolAddress((void**)&gX, g_Xh);
    cudaGetSymbolAddress((void**)&gW, g_Wh);

    cudaFuncSetAttribute(gemm_f16<1>, cudaFuncAttributeMaxDynamicSharedMemorySize,
                         GEMM_SMEM);
    cudaFuncSetAttribute(gemm_f16<0>, cudaFuncAttributeMaxDynamicSharedMemorySize,
                         GEMM_SMEM);
    cudaFuncSetAttribute(attn_f16, cudaFuncAttributeMaxDynamicSharedMemorySize,
                         ATT_SMEM);

    // 1) convert x + all W to fp16
    round_f16_kernel<<<12288, 256>>>(x, Wq, Wk, Wv, Wo);

    // 2) Q/K/V projections (grid.z selects weight/dst); fp16 out
    gemm_f16<1><<<dim3(8, 64, 3), 256, GEMM_SMEM>>>(gX, gW, gQ, gK, gV);

    // 3) RoPE (folds Q-scale)
    const int NPAIR = BATCH * NH * SEQ * (DK / 2);
    rope_kernel<<<dim3((NPAIR + 255) / 256, 2), 256>>>(tpos);

    // 4) attention (fp16, swizzled smem, h2exp2 + ones-mma rowsum)
    attn_f16<<<dim3(SEQ / 64, NH, BATCH), 128, ATT_SMEM>>>(nullptr);

    // 5) output projection (fp32 result)
    gemm_f16<0><<<dim3(8, 64, 1), 256, GEMM_SMEM>>>(gA, gW + (size_t)3 * DM * DM,
                                                    out, out, out);
}

// round 12
// speedup vs baseline: 1.2404x; 1.0417x over previous
#include <cuda_runtime.h>
#include <cuda_fp16.h>
#include <cstdint>

#define BATCH 2
#define SEQ 4096
#define NH 16
#define DK 64
#define DM 1024
#define L2E 1.4426950408889634f

#define QKV_ELEMS ((size_t)BATCH * NH * SEQ * DK)

// ---------------- scratch (no allocation allowed) ----------------
__device__ unsigned short g_Qh[QKV_ELEMS];
__device__ unsigned short g_Kh[QKV_ELEMS];
__device__ unsigned short g_Vh[QKV_ELEMS];
__device__ unsigned short g_Ah[(size_t)BATCH * SEQ * DM];
__device__ unsigned short g_Xh[(size_t)BATCH * SEQ * DM];
__device__ unsigned short g_Wh[(size_t)4 * DM * DM];

// ---------------- helpers ----------------
__device__ __forceinline__ uint32_t pkh(float lo, float hi) {
    uint32_t r;
    asm("cvt.rn.f16x2.f32 %0, %1, %2;" : "=r"(r) : "f"(hi), "f"(lo));
    return r;
}
__device__ __forceinline__ uint32_t h2exp2(uint32_t x) {
    uint32_t r;
    asm("ex2.approx.f16x2 %0, %1;" : "=r"(r) : "r"(x));
    return r;
}
__device__ __forceinline__ uint32_t smem_u32(const void* p) {
    uint32_t a;
    asm("{ .reg .u64 t; cvta.to.shared.u64 t, %1; cvt.u32.u64 %0, t; }"
        : "=r"(a) : "l"(p));
    return a;
}
__device__ __forceinline__ void cp16(uint32_t dst, const void* src) {
    asm volatile("cp.async.cg.shared.global [%0], [%1], 16;" :: "r"(dst), "l"(src));
}
__device__ __forceinline__ void cp_commit() {
    asm volatile("cp.async.commit_group;" ::: "memory");
}
template <int N>
__device__ __forceinline__ void cp_wait() {
    asm volatile("cp.async.wait_group %0;" :: "n"(N) : "memory");
}
__device__ __forceinline__ uint32_t swzb(uint32_t o) {   // 128B-row swizzle
    return o ^ ((o >> 3) & 0x70);
}
__device__ __forceinline__ void ldsm4(uint32_t& r0, uint32_t& r1, uint32_t& r2,
                                      uint32_t& r3, uint32_t a) {
    asm volatile("ldmatrix.sync.aligned.m8n8.x4.shared.b16 {%0,%1,%2,%3}, [%4];"
                 : "=r"(r0), "=r"(r1), "=r"(r2), "=r"(r3) : "r"(a));
}
__device__ __forceinline__ void ldsm4t(uint32_t& r0, uint32_t& r1, uint32_t& r2,
                                       uint32_t& r3, uint32_t a) {
    asm volatile("ldmatrix.sync.aligned.m8n8.x4.trans.shared.b16 {%0,%1,%2,%3}, [%4];"
                 : "=r"(r0), "=r"(r1), "=r"(r2), "=r"(r3) : "r"(a));
}
__device__ __forceinline__ void mma16(float c[4], uint32_t a0, uint32_t a1,
                                      uint32_t a2, uint32_t a3,
                                      uint32_t b0, uint32_t b1) {
    asm volatile(
        "mma.sync.aligned.m16n8k16.row.col.f32.f16.f16.f32 "
        "{%0,%1,%2,%3}, {%4,%5,%6,%7}, {%8,%9}, {%0,%1,%2,%3};"
        : "+f"(c[0]), "+f"(c[1]), "+f"(c[2]), "+f"(c[3])
        : "r"(a0), "r"(a1), "r"(a2), "r"(a3), "r"(b0), "r"(b1));
}

// ---------------- convert x + all W to fp16 ----------------
__global__ __launch_bounds__(256) void round_f16_kernel(
    const float* __restrict__ x, const float* __restrict__ Wq,
    const float* __restrict__ Wk, const float* __restrict__ Wv,
    const float* __restrict__ Wo) {
    size_t i4 = (size_t)blockIdx.x * 256 + threadIdx.x;  // float4 index
    const float4* src;
    uint2* dst;
    if (i4 < 2097152) {
        src = (const float4*)x + i4;
        dst = (uint2*)g_Xh + i4;
    } else {
        size_t r = i4 - 2097152;
        int j = (int)(r >> 18);
        size_t o = r & 262143;
        const float* w = (j == 0) ? Wq : (j == 1) ? Wk : (j == 2) ? Wv : Wo;
        src = (const float4*)w + o;
        dst = (uint2*)g_Wh + (size_t)j * 262144 + o;
    }
    float4 v = *src;
    *dst = make_uint2(pkh(v.x, v.y), pkh(v.z, v.w));
}

// ---------------- fp16 mma GEMM: k-block 64, swizzled 128B rows ------------
// C = A(Mx1024) * W(1024x1024)^T, tile 128x128, 2-stage cp.async, ldmatrix.
// MODE 0: fp32 row-major C.
// MODE 1: fp16 scatter [b][h][s][64]; RoPE fused in epilogue for z=0 (Q, with
//         qscale) and z=1 (K); z=2 (V) stored plain.
#define GSTAGE 32768
#define GEMM_SMEM (2 * GSTAGE)

template <int MODE>
__global__ __launch_bounds__(256, 2) void gemm_f16(
    const unsigned short* __restrict__ Abase,
    const unsigned short* __restrict__ Wbase,
    void* C0, void* C1, void* C2, const int* __restrict__ pos) {
    extern __shared__ __align__(16) char smraw[];
    const uint32_t smb = smem_u32(smraw);

    const int tid = threadIdx.x, wid = tid >> 5, lane = tid & 31;
    const int g = lane >> 2, tig = lane & 3;
    const int wm = (wid & 1) * 64, wn = (wid >> 1) * 32;
    const int z = blockIdx.z;
    const int m0 = blockIdx.y * 128, n0 = blockIdx.x * 128;
    const unsigned short* W = Wbase + (size_t)z * (DM * DM);
    void* C = (z == 0) ? C0 : (z == 1) ? C1 : C2;

    float acc[4][4][4];
#pragma unroll
    for (int mt = 0; mt < 4; mt++)
#pragma unroll
        for (int nt = 0; nt < 4; nt++)
#pragma unroll
            for (int k = 0; k < 4; k++) acc[mt][nt][k] = 0.f;

    const int a_r = (lane & 7) + ((lane >> 3) & 1) * 8;
    const int a_c = (lane >> 4) << 3;
    const int lr8 = tid >> 3, lc8 = (tid & 7);

    auto fill = [&](int s) {
        const uint32_t st = smb + (uint32_t)(s & 1) * GSTAGE;
        const int kb = s * 64;
#pragma unroll
        for (int i = 0; i < 4; i++) {
            int r = lr8 + i * 32;
            cp16(st + swzb(r * 128 + lc8 * 16),
                 Abase + (size_t)(m0 + r) * DM + kb + lc8 * 8);
        }
#pragma unroll
        for (int i = 0; i < 4; i++) {
            int r = lr8 + i * 32;
            cp16(st + 16384 + swzb(r * 128 + lc8 * 16),
                 W + (size_t)(n0 + r) * DM + kb + lc8 * 8);
        }
        cp_commit();
    };

    fill(0);

    for (int s = 0; s < 16; s++) {
        if (s + 1 < 16) {
            fill(s + 1);
            cp_wait<1>();
        } else {
            cp_wait<0>();
        }
        __syncthreads();
        const uint32_t asb = smb + (uint32_t)(s & 1) * GSTAGE;
        const uint32_t wsb = asb + 16384;

#pragma unroll
        for (int kk = 0; kk < 64; kk += 16) {
            uint32_t a[4][4], b[2][4];
#pragma unroll
            for (int mt = 0; mt < 4; mt++) {
                int ar = wm + mt * 16 + a_r;
                ldsm4(a[mt][0], a[mt][1], a[mt][2], a[mt][3],
                      asb + swzb((uint32_t)(ar * 128 + (kk + a_c) * 2)));
            }
#pragma unroll
            for (int j = 0; j < 2; j++) {
                int nr = wn + j * 16 + (lane & 7) + ((lane >> 4) << 3);
                int kc = kk + ((lane >> 3) & 1) * 8;
                ldsm4(b[j][0], b[j][1], b[j][2], b[j][3],
                      wsb + swzb((uint32_t)(nr * 128 + kc * 2)));
            }
#pragma unroll
            for (int mt = 0; mt < 4; mt++)
#pragma unroll
                for (int j = 0; j < 2; j++) {
                    mma16(acc[mt][2 * j], a[mt][0], a[mt][1], a[mt][2], a[mt][3],
                          b[j][0], b[j][1]);
                    mma16(acc[mt][2 * j + 1], a[mt][0], a[mt][1], a[mt][2], a[mt][3],
                          b[j][2], b[j][3]);
                }
        }
        __syncthreads();
    }

#pragma unroll
    for (int mt = 0; mt < 4; mt++) {
        const int r0 = m0 + wm + mt * 16 + g;
        const int r1 = r0 + 8;
        int p0 = 0, p1 = 0;
        if (MODE == 1 && z < 2) {
            p0 = pos[r0];      // pos is [B,SEQ] contiguous; r0 indexes it flat
            p1 = pos[r1];
        }
#pragma unroll
        for (int nt = 0; nt < 4; nt++) {
            int cc = n0 + wn + nt * 8 + 2 * tig;
            if (MODE == 0) {
                float* Cf = (float*)C;
                *(float2*)&Cf[(size_t)r0 * DM + cc] =
                    make_float2(acc[mt][nt][0], acc[mt][nt][1]);
                *(float2*)&Cf[(size_t)r1 * DM + cc] =
                    make_float2(acc[mt][nt][2], acc[mt][nt][3]);
            } else {
                unsigned short* Ch = (unsigned short*)C;
                int h = cc >> 6, d = cc & 63;
                float e0 = acc[mt][nt][0], o0 = acc[mt][nt][1];
                float e1 = acc[mt][nt][2], o1 = acc[mt][nt][3];
                if (z < 2) {  // fused RoPE: (e,o) is the even/odd pair d, d+1
                    int j = d >> 1;
                    float freq = exp2f(-(float)j * (13.287712379549449f / 32.f));
                    float sn0, cs0, sn1, cs1;
                    sincosf((float)p0 * freq, &sn0, &cs0);
                    sincosf((float)p1 * freq, &sn1, &cs1);
                    float ne0 = e0 * cs0 - o0 * sn0, no0 = e0 * sn0 + o0 * cs0;
                    float ne1 = e1 * cs1 - o1 * sn1, no1 = e1 * sn1 + o1 * cs1;
                    if (z == 0) {
                        const float qs = 0.125f * L2E;
                        ne0 *= qs; no0 *= qs; ne1 *= qs; no1 *= qs;
                    }
                    e0 = ne0; o0 = no0; e1 = ne1; o1 = no1;
                }
                int b0i = r0 >> 12, s0 = r0 & (SEQ - 1);
                int b1i = r1 >> 12, s1 = r1 & (SEQ - 1);
                *(uint32_t*)(Ch + ((size_t)(b0i * NH + h) * SEQ + s0) * DK + d) =
                    pkh(e0, o0);
                *(uint32_t*)(Ch + ((size_t)(b1i * NH + h) * SEQ + s1) * DK + d) =
                    pkh(e1, o1);
            }
        }
    }
}

// ---------------- causal flash attention, fp16, skip-rescale ---------------
// Br=Bc=64, 128 threads (4 warps x 16 rows). Q frags in registers.
// smem: 5 tiles x 8192B (Q | K0 K1 | V0 V1), 128B swizzled rows -> 40960 B.
#define AT_K 8192
#define AT_V 24576
#define ATT_SMEM 40960

__global__ __launch_bounds__(128, 5) void attn_f16(float* dummy) {
    extern __shared__ __align__(16) char asm_raw[];
    const uint32_t smb = smem_u32(asm_raw);

    const int qt = 63 - (int)blockIdx.x;
    const int h = blockIdx.y;
    const int b = blockIdx.z;
    const int tid = threadIdx.x;
    const int wid = tid >> 5, lane = tid & 31;
    const int g = lane >> 2, tig = lane & 3;
    const int wr = wid * 16;

    const size_t bh = (size_t)(b * NH + h) * SEQ;
    const unsigned short* Qb = g_Qh + (bh + (size_t)qt * 64) * DK;
    const unsigned short* Kb = g_Kh + bh * DK;
    const unsigned short* Vb = g_Vh + bh * DK;

    const int l_r = (lane & 7) + ((lane >> 3) & 1) * 8;
    const int l_c8 = (lane >> 4) << 3;

    auto prefetch = [&](int kt, int buf) {
        const uint32_t kst = smb + AT_K + buf * 8192;
        const uint32_t vst = smb + AT_V + buf * 8192;
#pragma unroll
        for (int i = 0; i < 4; i++) {
            int q = tid + i * 128;
            int r = q >> 3, c = q & 7;
            cp16(kst + swzb(r * 128 + c * 16),
                 Kb + (size_t)(kt * 64 + r) * DK + c * 8);
        }
#pragma unroll
        for (int i = 0; i < 4; i++) {
            int q = tid + i * 128;
            int r = q >> 3, c = q & 7;
            cp16(vst + swzb(r * 128 + c * 16),
                 Vb + (size_t)(kt * 64 + r) * DK + c * 8);
        }
        cp_commit();
    };

    // Q tile -> swizzled smem (once)
#pragma unroll
    for (int p = 0; p < 4; p++) {
        int idx = p * 128 + tid;
        int r = idx >> 3, c = idx & 7;
        *(uint4*)(asm_raw + swzb(r * 128 + c * 16)) =
            *(const uint4*)(Qb + (size_t)r * DK + c * 8);
    }
    prefetch(0, 0);
    __syncthreads();

    // hoist Q fragments (4 k-chunks of 16)
    uint32_t qf[4][4];
#pragma unroll
    for (int kq = 0; kq < 4; kq++) {
        int qr = wr + l_r;
        int qcb = (kq * 16 + l_c8) * 2;
        ldsm4(qf[kq][0], qf[kq][1], qf[kq][2], qf[kq][3],
              smb + swzb((uint32_t)(qr * 128 + qcb)));
    }

    float oacc[8][4];
    float lacc[4] = {0.f, 0.f, 0.f, 0.f};
    float m0 = -1e30f, m1 = -1e30f;
#pragma unroll
    for (int nt = 0; nt < 8; nt++)
#pragma unroll
        for (int k = 0; k < 4; k++) oacc[nt][k] = 0.f;

    const uint32_t ONESH = 0x3C003C00u;      // {1.0h, 1.0h}

    const int ntiles = qt + 1;
    for (int kt = 0; kt < ntiles; kt++) {
        const int buf = kt & 1;
        __syncthreads();
        if (kt + 1 < ntiles) {
            prefetch(kt + 1, buf ^ 1);
            cp_wait<1>();
        } else {
            cp_wait<0>();
        }
        __syncthreads();

        const uint32_t ksb = smb + AT_K + buf * 8192;
        const uint32_t vsb = smb + AT_V + buf * 8192;

        // S = Q K^T
        float sacc[8][4];
#pragma unroll
        for (int nt = 0; nt < 8; nt++)
#pragma unroll
            for (int k = 0; k < 4; k++) sacc[nt][k] = 0.f;

#pragma unroll
        for (int kq = 0; kq < 4; kq++) {
            const int kk = kq * 16;
#pragma unroll
            for (int j = 0; j < 4; j++) {
                int nr = j * 16 + (lane & 7) + l_c8;
                int kcb = (kk + ((lane >> 3) & 1) * 8) * 2;
                uint32_t b0, b1, b2, b3;
                ldsm4(b0, b1, b2, b3, ksb + swzb((uint32_t)(nr * 128 + kcb)));
                mma16(sacc[2 * j], qf[kq][0], qf[kq][1], qf[kq][2], qf[kq][3], b0, b1);
                mma16(sacc[2 * j + 1], qf[kq][0], qf[kq][1], qf[kq][2], qf[kq][3], b2, b3);
            }
        }

        if (kt == qt) {  // causal mask on diagonal tile
#pragma unroll
            for (int nt = 0; nt < 8; nt++) {
                int c0 = nt * 8 + 2 * tig, c1 = c0 + 1;
                if (c0 > wr + g) sacc[nt][0] = -1e30f;
                if (c1 > wr + g) sacc[nt][1] = -1e30f;
                if (c0 > wr + g + 8) sacc[nt][2] = -1e30f;
                if (c1 > wr + g + 8) sacc[nt][3] = -1e30f;
            }
        }

        // online softmax: row-max (quad shuffles)
        float tm0 = -1e30f, tm1 = -1e30f;
#pragma unroll
        for (int nt = 0; nt < 8; nt++) {
            tm0 = fmaxf(tm0, fmaxf(sacc[nt][0], sacc[nt][1]));
            tm1 = fmaxf(tm1, fmaxf(sacc[nt][2], sacc[nt][3]));
        }
        tm0 = fmaxf(tm0, __shfl_xor_sync(0xffffffffu, tm0, 1));
        tm0 = fmaxf(tm0, __shfl_xor_sync(0xffffffffu, tm0, 2));
        tm1 = fmaxf(tm1, __shfl_xor_sync(0xffffffffu, tm1, 1));
        tm1 = fmaxf(tm1, __shfl_xor_sync(0xffffffffu, tm1, 2));

        const float mo0 = m0, mo1 = m1;
        float mn0 = fmaxf(m0, tm0), mn1 = fmaxf(m1, tm1);
        m0 = mn0; m1 = mn1;

        uint32_t ph[8][2];
#pragma unroll
        for (int nt = 0; nt < 8; nt++) {
            ph[nt][0] = h2exp2(pkh(sacc[nt][0] - mn0, sacc[nt][1] - mn0));
            ph[nt][1] = h2exp2(pkh(sacc[nt][2] - mn1, sacc[nt][3] - mn1));
        }

        // rescale only when some row's max actually grew (warp-uniform vote)
        bool stable = (mn0 == mo0) && (mn1 == mo1);
        if (!__all_sync(0xffffffffu, stable)) {
            float al0 = exp2f(mo0 - mn0), al1 = exp2f(mo1 - mn1);
            lacc[0] *= al0; lacc[2] *= al1;
#pragma unroll
            for (int nt = 0; nt < 8; nt++) {
                oacc[nt][0] *= al0; oacc[nt][1] *= al0;
                oacc[nt][2] *= al1; oacc[nt][3] *= al1;
            }
        }

        // O += P V, and rowsum += P @ ones (tensor pipe)
#pragma unroll
        for (int kc = 0; kc < 64; kc += 16) {
            const int e = kc >> 3;
            uint32_t a0 = ph[e][0];
            uint32_t a1 = ph[e][1];
            uint32_t a2 = ph[e + 1][0];
            uint32_t a3 = ph[e + 1][1];
            mma16(lacc, a0, a1, a2, a3, ONESH, ONESH);
#pragma unroll
            for (int j = 0; j < 4; j++) {
                int vr = kc + l_r;
                int vcb = (j * 16 + l_c8) * 2;
                uint32_t b0, b1, b2, b3;
                ldsm4t(b0, b1, b2, b3, vsb + swzb((uint32_t)(vr * 128 + vcb)));
                mma16(oacc[2 * j], a0, a1, a2, a3, b0, b1);
                mma16(oacc[2 * j + 1], a0, a1, a2, a3, b2, b3);
            }
        }
    }

    // normalize + fp16 write [b][s][h][d] (feeds Wo GEMM)
    float inv0 = 1.f / lacc[0], inv1 = 1.f / lacc[2];
    int sg0 = qt * 64 + wr + g, sg1 = sg0 + 8;
#pragma unroll
    for (int nt = 0; nt < 8; nt++) {
        int d = nt * 8 + 2 * tig;
        *(uint32_t*)(g_Ah + (((size_t)b * SEQ + sg0) * NH + h) * DK + d) =
            pkh(oacc[nt][0] * inv0, oacc[nt][1] * inv0);
        *(uint32_t*)(g_Ah + (((size_t)b * SEQ + sg1) * NH + h) * DK + d) =
            pkh(oacc[nt][2] * inv1, oacc[nt][3] * inv1);
    }
    (void)dummy;
}

// ---------------- launch ----------------
extern "C" void kernel_launch(void* const* d_in, const int* in_sizes, int n_in,
                              void* d_out, int out_size) {
    const float* x = (const float*)d_in[0];
    const int* tpos = (const int*)d_in[1];
    const float* Wq = (const float*)d_in[2];
    const float* Wk = (const float*)d_in[3];
    const float* Wv = (const float*)d_in[4];
    const float* Wo = (const float*)d_in[5];
    float* out = (float*)d_out;

    unsigned short *gQ, *gK, *gV, *gA, *gX, *gW;
    cudaGetSymbolAddress((void**)&gQ, g_Qh);
    cudaGetSymbolAddress((void**)&gK, g_Kh);
    cudaGetSymbolAddress((void**)&gV, g_Vh);
    cudaGetSymbolAddress((void**)&gA, g_Ah);
    cudaGetSymbolAddress((void**)&gX, g_Xh);
    cudaGetSymbolAddress((void**)&gW, g_Wh);

    cudaFuncSetAttribute(gemm_f16<1>, cudaFuncAttributeMaxDynamicSharedMemorySize,
                         GEMM_SMEM);
    cudaFuncSetAttribute(gemm_f16<0>, cudaFuncAttributeMaxDynamicSharedMemorySize,
                         GEMM_SMEM);
    cudaFuncSetAttribute(attn_f16, cudaFuncAttributeMaxDynamicSharedMemorySize,
                         ATT_SMEM);

    // 1) convert x + all W to fp16
    round_f16_kernel<<<12288, 256>>>(x, Wq, Wk, Wv, Wo);

    // 2) Q/K/V projections with fused RoPE (z=0: Q+scale, z=1: K, z=2: V)
    gemm_f16<1><<<dim3(8, 64, 3), 256, GEMM_SMEM>>>(gX, gW, gQ, gK, gV, tpos);

    // 3) attention (fp16, swizzled smem, skip-rescale)
    attn_f16<<<dim3(SEQ / 64, NH, BATCH), 128, ATT_SMEM>>>(nullptr);

    // 4) output projection (fp32 result)
    gemm_f16<0><<<dim3(8, 64, 1), 256, GEMM_SMEM>>>(gA, gW + (size_t)3 * DM * DM,
                                                    out, out, out, tpos);
}

// round 14
// speedup vs baseline: 1.3389x; 1.0794x over previous
#include <cuda_runtime.h>
#include <cuda_fp16.h>
#include <cstdint>

#define BATCH 2
#define SEQ 4096
#define NH 16
#define DK 64
#define DM 1024
#define L2E 1.4426950408889634f

#define QKV_ELEMS ((size_t)BATCH * NH * SEQ * DK)

// ---------------- scratch (no allocation allowed) ----------------
__device__ unsigned short g_Qh[QKV_ELEMS];
__device__ unsigned short g_Kh[QKV_ELEMS];
__device__ unsigned short g_Vh[QKV_ELEMS];
__device__ unsigned short g_Ah[(size_t)BATCH * SEQ * DM];
__device__ unsigned short g_Xh[(size_t)BATCH * SEQ * DM];
__device__ unsigned short g_Wh[(size_t)4 * DM * DM];

// ---------------- helpers ----------------
__device__ __forceinline__ uint32_t pkh(float lo, float hi) {
    uint32_t r;
    asm("cvt.rn.f16x2.f32 %0, %1, %2;" : "=r"(r) : "f"(hi), "f"(lo));
    return r;
}
__device__ __forceinline__ uint32_t h2exp2(uint32_t x) {
    uint32_t r;
    asm("ex2.approx.f16x2 %0, %1;" : "=r"(r) : "r"(x));
    return r;
}
__device__ __forceinline__ uint32_t smem_u32(const void* p) {
    uint32_t a;
    asm("{ .reg .u64 t; cvta.to.shared.u64 t, %1; cvt.u32.u64 %0, t; }"
        : "=r"(a) : "l"(p));
    return a;
}
__device__ __forceinline__ void cp16(uint32_t dst, const void* src) {
    asm volatile("cp.async.cg.shared.global [%0], [%1], 16;" :: "r"(dst), "l"(src));
}
__device__ __forceinline__ void cp_commit() {
    asm volatile("cp.async.commit_group;" ::: "memory");
}
template <int N>
__device__ __forceinline__ void cp_wait() {
    asm volatile("cp.async.wait_group %0;" :: "n"(N) : "memory");
}
__device__ __forceinline__ uint32_t swzb(uint32_t o) {   // 128B-row swizzle
    return o ^ ((o >> 3) & 0x70);
}
__device__ __forceinline__ void ldsm4(uint32_t& r0, uint32_t& r1, uint32_t& r2,
                                      uint32_t& r3, uint32_t a) {
    asm volatile("ldmatrix.sync.aligned.m8n8.x4.shared.b16 {%0,%1,%2,%3}, [%4];"
                 : "=r"(r0), "=r"(r1), "=r"(r2), "=r"(r3) : "r"(a));
}
__device__ __forceinline__ void ldsm4t(uint32_t& r0, uint32_t& r1, uint32_t& r2,
                                       uint32_t& r3, uint32_t a) {
    asm volatile("ldmatrix.sync.aligned.m8n8.x4.trans.shared.b16 {%0,%1,%2,%3}, [%4];"
                 : "=r"(r0), "=r"(r1), "=r"(r2), "=r"(r3) : "r"(a));
}
__device__ __forceinline__ void mma16(float c[4], uint32_t a0, uint32_t a1,
                                      uint32_t a2, uint32_t a3,
                                      uint32_t b0, uint32_t b1) {
    asm volatile(
        "mma.sync.aligned.m16n8k16.row.col.f32.f16.f16.f32 "
        "{%0,%1,%2,%3}, {%4,%5,%6,%7}, {%8,%9}, {%0,%1,%2,%3};"
        : "+f"(c[0]), "+f"(c[1]), "+f"(c[2]), "+f"(c[3])
        : "r"(a0), "r"(a1), "r"(a2), "r"(a3), "r"(b0), "r"(b1));
}

// ---------------- convert x + all W to fp16 ----------------
__global__ __launch_bounds__(256) void round_f16_kernel(
    const float* __restrict__ x, const float* __restrict__ Wq,
    const float* __restrict__ Wk, const float* __restrict__ Wv,
    const float* __restrict__ Wo) {
    size_t i4 = (size_t)blockIdx.x * 256 + threadIdx.x;  // float4 index
    const float4* src;
    uint2* dst;
    if (i4 < 2097152) {
        src = (const float4*)x + i4;
        dst = (uint2*)g_Xh + i4;
    } else {
        size_t r = i4 - 2097152;
        int j = (int)(r >> 18);
        size_t o = r & 262143;
        const float* w = (j == 0) ? Wq : (j == 1) ? Wk : (j == 2) ? Wv : Wo;
        src = (const float4*)w + o;
        dst = (uint2*)g_Wh + (size_t)j * 262144 + o;
    }
    float4 v = *src;
    *dst = make_uint2(pkh(v.x, v.y), pkh(v.z, v.w));
}

// ---------------- fp16 mma GEMM: k-block 64, swizzled 128B rows ------------
// C = A(Mx1024) * W(1024x1024)^T, tile 128x128, 2-stage cp.async, ldmatrix.
// MODE 0: fp32 row-major C.
// MODE 1: fp16 scatter [b][h][s][64]; RoPE fused in epilogue for z=0 (Q, with
//         qscale) and z=1 (K); z=2 (V) stored plain.
#define GSTAGE 32768
#define GEMM_SMEM (2 * GSTAGE)

template <int MODE>
__global__ __launch_bounds__(256, 2) void gemm_f16(
    const unsigned short* __restrict__ Abase,
    const unsigned short* __restrict__ Wbase,
    void* C0, void* C1, void* C2, const int* __restrict__ pos) {
    extern __shared__ __align__(16) char smraw[];
    const uint32_t smb = smem_u32(smraw);

    const int tid = threadIdx.x, wid = tid >> 5, lane = tid & 31;
    const int g = lane >> 2, tig = lane & 3;
    const int wm = (wid & 1) * 64, wn = (wid >> 1) * 32;
    const int z = blockIdx.z;
    const int m0 = blockIdx.y * 128, n0 = blockIdx.x * 128;
    const unsigned short* W = Wbase + (size_t)z * (DM * DM);
    void* C = (z == 0) ? C0 : (z == 1) ? C1 : C2;

    float acc[4][4][4];
#pragma unroll
    for (int mt = 0; mt < 4; mt++)
#pragma unroll
        for (int nt = 0; nt < 4; nt++)
#pragma unroll
            for (int k = 0; k < 4; k++) acc[mt][nt][k] = 0.f;

    const int a_r = (lane & 7) + ((lane >> 3) & 1) * 8;
    const int a_c = (lane >> 4) << 3;
    const int lr8 = tid >> 3, lc8 = (tid & 7);

    auto fill = [&](int s) {
        const uint32_t st = smb + (uint32_t)(s & 1) * GSTAGE;
        const int kb = s * 64;
#pragma unroll
        for (int i = 0; i < 4; i++) {
            int r = lr8 + i * 32;
            cp16(st + swzb(r * 128 + lc8 * 16),
                 Abase + (size_t)(m0 + r) * DM + kb + lc8 * 8);
        }
#pragma unroll
        for (int i = 0; i < 4; i++) {
            int r = lr8 + i * 32;
            cp16(st + 16384 + swzb(r * 128 + lc8 * 16),
                 W + (size_t)(n0 + r) * DM + kb + lc8 * 8);
        }
        cp_commit();
    };

    fill(0);

    for (int s = 0; s < 16; s++) {
        if (s + 1 < 16) {
            fill(s + 1);
            cp_wait<1>();
        } else {
            cp_wait<0>();
        }
        __syncthreads();
        const uint32_t asb = smb + (uint32_t)(s & 1) * GSTAGE;
        const uint32_t wsb = asb + 16384;

#pragma unroll
        for (int kk = 0; kk < 64; kk += 16) {
            uint32_t a[4][4], b[2][4];
#pragma unroll
            for (int mt = 0; mt < 4; mt++) {
                int ar = wm + mt * 16 + a_r;
                ldsm4(a[mt][0], a[mt][1], a[mt][2], a[mt][3],
                      asb + swzb((uint32_t)(ar * 128 + (kk + a_c) * 2)));
            }
#pragma unroll
            for (int j = 0; j < 2; j++) {
                int nr = wn + j * 16 + (lane & 7) + ((lane >> 4) << 3);
                int kc = kk + ((lane >> 3) & 1) * 8;
                ldsm4(b[j][0], b[j][1], b[j][2], b[j][3],
                      wsb + swzb((uint32_t)(nr * 128 + kc * 2)));
            }
#pragma unroll
            for (int mt = 0; mt < 4; mt++)
#pragma unroll
                for (int j = 0; j < 2; j++) {
                    mma16(acc[mt][2 * j], a[mt][0], a[mt][1], a[mt][2], a[mt][3],
                          b[j][0], b[j][1]);
                    mma16(acc[mt][2 * j + 1], a[mt][0], a[mt][1], a[mt][2], a[mt][3],
                          b[j][2], b[j][3]);
                }
        }
        __syncthreads();
    }

#pragma unroll
    for (int mt = 0; mt < 4; mt++) {
        const int r0 = m0 + wm + mt * 16 + g;
        const int r1 = r0 + 8;
        int p0 = 0, p1 = 0;
        if (MODE == 1 && z < 2) {
            p0 = pos[r0];
            p1 = pos[r1];
        }
#pragma unroll
        for (int nt = 0; nt < 4; nt++) {
            int cc = n0 + wn + nt * 8 + 2 * tig;
            if (MODE == 0) {
                float* Cf = (float*)C;
                *(float2*)&Cf[(size_t)r0 * DM + cc] =
                    make_float2(acc[mt][nt][0], acc[mt][nt][1]);
                *(float2*)&Cf[(size_t)r1 * DM + cc] =
                    make_float2(acc[mt][nt][2], acc[mt][nt][3]);
            } else {
                unsigned short* Ch = (unsigned short*)C;
                int h = cc >> 6, d = cc & 63;
                float e0 = acc[mt][nt][0], o0 = acc[mt][nt][1];
                float e1 = acc[mt][nt][2], o1 = acc[mt][nt][3];
                if (z < 2) {  // fused RoPE
                    int j = d >> 1;
                    float freq = exp2f(-(float)j * (13.287712379549449f / 32.f));
                    float sn0, cs0, sn1, cs1;
                    sincosf((float)p0 * freq, &sn0, &cs0);
                    sincosf((float)p1 * freq, &sn1, &cs1);
                    float ne0 = e0 * cs0 - o0 * sn0, no0 = e0 * sn0 + o0 * cs0;
                    float ne1 = e1 * cs1 - o1 * sn1, no1 = e1 * sn1 + o1 * cs1;
                    if (z == 0) {
                        const float qs = 0.125f * L2E;
                        ne0 *= qs; no0 *= qs; ne1 *= qs; no1 *= qs;
                    }
                    e0 = ne0; o0 = no0; e1 = ne1; o1 = no1;
                }
                int b0i = r0 >> 12, s0 = r0 & (SEQ - 1);
                int b1i = r1 >> 12, s1 = r1 & (SEQ - 1);
                *(uint32_t*)(Ch + ((size_t)(b0i * NH + h) * SEQ + s0) * DK + d) =
                    pkh(e0, o0);
                *(uint32_t*)(Ch + ((size_t)(b1i * NH + h) * SEQ + s1) * DK + d) =
                    pkh(e1, o1);
            }
        }
    }
}

// ---------------- causal flash attention: 3-buffer ring, 1 barrier/tile ----
// Br=Bc=64, 128 threads (4 warps x 16 rows). Q frags in registers.
// smem: Q 8K | K0 K1 K2 (8K each) | V0 V1 V2 (8K each) = 57344 B -> 4 CTA/SM.
#define AT_K 8192
#define AT_V 32768
#define ATT_SMEM 57344

__global__ __launch_bounds__(128, 4) void attn_f16(float* dummy) {
    extern __shared__ __align__(16) char asm_raw[];
    const uint32_t smb = smem_u32(asm_raw);

    const int qt = 63 - (int)blockIdx.x;
    const int h = blockIdx.y;
    const int b = blockIdx.z;
    const int tid = threadIdx.x;
    const int wid = tid >> 5, lane = tid & 31;
    const int g = lane >> 2, tig = lane & 3;
    const int wr = wid * 16;

    const size_t bh = (size_t)(b * NH + h) * SEQ;
    const unsigned short* Qb = g_Qh + (bh + (size_t)qt * 64) * DK;
    const unsigned short* Kb = g_Kh + bh * DK;
    const unsigned short* Vb = g_Vh + bh * DK;

    const int l_r = (lane & 7) + ((lane >> 3) & 1) * 8;
    const int l_c8 = (lane >> 4) << 3;

    auto prefetch = [&](int kt, int buf) {
        const uint32_t kst = smb + AT_K + buf * 8192;
        const uint32_t vst = smb + AT_V + buf * 8192;
#pragma unroll
        for (int i = 0; i < 4; i++) {
            int q = tid + i * 128;
            int r = q >> 3, c = q & 7;
            cp16(kst + swzb(r * 128 + c * 16),
                 Kb + (size_t)(kt * 64 + r) * DK + c * 8);
        }
#pragma unroll
        for (int i = 0; i < 4; i++) {
            int q = tid + i * 128;
            int r = q >> 3, c = q & 7;
            cp16(vst + swzb(r * 128 + c * 16),
                 Vb + (size_t)(kt * 64 + r) * DK + c * 8);
        }
        cp_commit();
    };

    // Q tile -> swizzled smem (once)
#pragma unroll
    for (int p = 0; p < 4; p++) {
        int idx = p * 128 + tid;
        int r = idx >> 3, c = idx & 7;
        *(uint4*)(asm_raw + swzb(r * 128 + c * 16)) =
            *(const uint4*)(Qb + (size_t)r * DK + c * 8);
    }
    const int ntiles = qt + 1;
    prefetch(0, 0);
    if (ntiles > 1) {
        prefetch(1, 1);
        cp_wait<1>();   // two groups committed; tile 0 guaranteed arrived
    } else {
        cp_wait<0>();   // qt==0: only one group — MUST drain it fully
    }
    __syncthreads();

    // hoist Q fragments (4 k-chunks of 16)
    uint32_t qf[4][4];
#pragma unroll
    for (int kq = 0; kq < 4; kq++) {
        int qr = wr + l_r;
        int qcb = (kq * 16 + l_c8) * 2;
        ldsm4(qf[kq][0], qf[kq][1], qf[kq][2], qf[kq][3],
              smb + swzb((uint32_t)(qr * 128 + qcb)));
    }

    float oacc[8][4];
    float lacc[4] = {0.f, 0.f, 0.f, 0.f};
    float m0 = -1e30f, m1 = -1e30f;
#pragma unroll
    for (int nt = 0; nt < 8; nt++)
#pragma unroll
        for (int k = 0; k < 4; k++) oacc[nt][k] = 0.f;

    const uint32_t ONESH = 0x3C003C00u;      // {1.0h, 1.0h}

    for (int kt = 0; kt < ntiles; kt++) {
        const int buf = kt - (kt / 3) * 3;   // kt % 3
        const uint32_t ksb = smb + AT_K + buf * 8192;
        const uint32_t vsb = smb + AT_V + buf * 8192;

        // 1) S = Q K^T  (Ks[kt] visible since previous iteration's barrier)
        float sacc[8][4];
#pragma unroll
        for (int nt = 0; nt < 8; nt++)
#pragma unroll
            for (int k = 0; k < 4; k++) sacc[nt][k] = 0.f;

#pragma unroll
        for (int kq = 0; kq < 4; kq++) {
            const int kk = kq * 16;
#pragma unroll
            for (int j = 0; j < 4; j++) {
                int nr = j * 16 + (lane & 7) + l_c8;
                int kcb = (kk + ((lane >> 3) & 1) * 8) * 2;
                uint32_t b0, b1, b2, b3;
                ldsm4(b0, b1, b2, b3, ksb + swzb((uint32_t)(nr * 128 + kcb)));
                mma16(sacc[2 * j], qf[kq][0], qf[kq][1], qf[kq][2], qf[kq][3], b0, b1);
                mma16(sacc[2 * j + 1], qf[kq][0], qf[kq][1], qf[kq][2], qf[kq][3], b2, b3);
            }
        }

        // 2) make tile kt+1 visible + license buf (kt+2)%3 == (kt-1)%3 reuse
        cp_wait<0>();
        __syncthreads();   // ONLY barrier this iteration

        // 3) prefetch tile kt+2 (overwrites buf last read at iter kt-1,
        //    protected by the barrier above)
        if (kt + 2 < ntiles) prefetch(kt + 2, (kt + 2) % 3);

        if (kt == qt) {  // causal mask on diagonal tile
#pragma unroll
            for (int nt = 0; nt < 8; nt++) {
                int c0 = nt * 8 + 2 * tig, c1 = c0 + 1;
                if (c0 > wr + g) sacc[nt][0] = -1e30f;
                if (c1 > wr + g) sacc[nt][1] = -1e30f;
                if (c0 > wr + g + 8) sacc[nt][2] = -1e30f;
                if (c1 > wr + g + 8) sacc[nt][3] = -1e30f;
            }
        }

        // 4) online softmax: row-max (quad shuffles)
        float tm0 = -1e30f, tm1 = -1e30f;
#pragma unroll
        for (int nt = 0; nt < 8; nt++) {
            tm0 = fmaxf(tm0, fmaxf(sacc[nt][0], sacc[nt][1]));
            tm1 = fmaxf(tm1, fmaxf(sacc[nt][2], sacc[nt][3]));
        }
        tm0 = fmaxf(tm0, __shfl_xor_sync(0xffffffffu, tm0, 1));
        tm0 = fmaxf(tm0, __shfl_xor_sync(0xffffffffu, tm0, 2));
        tm1 = fmaxf(tm1, __shfl_xor_sync(0xffffffffu, tm1, 1));
        tm1 = fmaxf(tm1, __shfl_xor_sync(0xffffffffu, tm1, 2));

        const float mo0 = m0, mo1 = m1;
        float mn0 = fmaxf(m0, tm0), mn1 = fmaxf(m1, tm1);
        m0 = mn0; m1 = mn1;

        uint32_t ph[8][2];
#pragma unroll
        for (int nt = 0; nt < 8; nt++) {
            ph[nt][0] = h2exp2(pkh(sacc[nt][0] - mn0, sacc[nt][1] - mn0));
            ph[nt][1] = h2exp2(pkh(sacc[nt][2] - mn1, sacc[nt][3] - mn1));
        }

        // rescale only when some row's max actually grew (warp-uniform vote)
        bool stable = (mn0 == mo0) && (mn1 == mo1);
        if (!__all_sync(0xffffffffu, stable)) {
            float al0 = exp2f(mo0 - mn0), al1 = exp2f(mo1 - mn1);
            lacc[0] *= al0; lacc[2] *= al1;
#pragma unroll
            for (int nt = 0; nt < 8; nt++) {
                oacc[nt][0] *= al0; oacc[nt][1] *= al0;
                oacc[nt][2] *= al1; oacc[nt][3] *= al1;
            }
        }

        // 5) O += P V, rowsum += P @ ones (tensor pipe)
#pragma unroll
        for (int kc = 0; kc < 64; kc += 16) {
            const int e = kc >> 3;
            uint32_t a0 = ph[e][0];
            uint32_t a1 = ph[e][1];
            uint32_t a2 = ph[e + 1][0];
            uint32_t a3 = ph[e + 1][1];
            mma16(lacc, a0, a1, a2, a3, ONESH, ONESH);
#pragma unroll
            for (int j = 0; j < 4; j++) {
                int vr = kc + l_r;
                int vcb = (j * 16 + l_c8) * 2;
                uint32_t b0, b1, b2, b3;
                ldsm4t(b0, b1, b2, b3, vsb + swzb((uint32_t)(vr * 128 + vcb)));
                mma16(oacc[2 * j], a0, a1, a2, a3, b0, b1);
                mma16(oacc[2 * j + 1], a0, a1, a2, a3, b2, b3);
            }
        }
    }

    // normalize + fp16 write [b][s][h][d] (feeds Wo GEMM)
    float inv0 = 1.f / lacc[0], inv1 = 1.f / lacc[2];
    int sg0 = qt * 64 + wr + g, sg1 = sg0 + 8;
#pragma unroll
    for (int nt = 0; nt < 8; nt++) {
        int d = nt * 8 + 2 * tig;
        *(uint32_t*)(g_Ah + (((size_t)b * SEQ + sg0) * NH + h) * DK + d) =
            pkh(oacc[nt][0] * inv0, oacc[nt][1] * inv0);
        *(uint32_t*)(g_Ah + (((size_t)b * SEQ + sg1) * NH + h) * DK + d) =
            pkh(oacc[nt][2] * inv1, oacc[nt][3] * inv1);
    }
    (void)dummy;
}

// ---------------- launch ----------------
extern "C" void kernel_launch(void* const* d_in, const int* in_sizes, int n_in,
                              void* d_out, int out_size) {
    const float* x = (const float*)d_in[0];
    const int* tpos = (const int*)d_in[1];
    const float* Wq = (const float*)d_in[2];
    const float* Wk = (const float*)d_in[3];
    const float* Wv = (const float*)d_in[4];
    const float* Wo = (const float*)d_in[5];
    float* out = (float*)d_out;

    unsigned short *gQ, *gK, *gV, *gA, *gX, *gW;
    cudaGetSymbolAddress((void**)&gQ, g_Qh);
    cudaGetSymbolAddress((void**)&gK, g_Kh);
    cudaGetSymbolAddress((void**)&gV, g_Vh);
    cudaGetSymbolAddress((void**)&gA, g_Ah);
    cudaGetSymbolAddress((void**)&gX, g_Xh);
    cudaGetSymbolAddress((void**)&gW, g_Wh);

    cudaFuncSetAttribute(gemm_f16<1>, cudaFuncAttributeMaxDynamicSharedMemorySize,
                         GEMM_SMEM);
    cudaFuncSetAttribute(gemm_f16<0>, cudaFuncAttributeMaxDynamicSharedMemorySize,
                         GEMM_SMEM);
    cudaFuncSetAttribute(attn_f16, cudaFuncAttributeMaxDynamicSharedMemorySize,
                         ATT_SMEM);

    // 1) convert x + all W to fp16
    round_f16_kernel<<<12288, 256>>>(x, Wq, Wk, Wv, Wo);

    // 2) Q/K/V projections with fused RoPE (z=0: Q+scale, z=1: K, z=2: V)
    gemm_f16<1><<<dim3(8, 64, 3), 256, GEMM_SMEM>>>(gX, gW, gQ, gK, gV, tpos);

    // 3) attention (3-buffer ring, single barrier per tile)
    attn_f16<<<dim3(SEQ / 64, NH, BATCH), 128, ATT_SMEM>>>(nullptr);

    // 4) output projection (fp32 result)
    gemm_f16<0><<<dim3(8, 64, 1), 256, GEMM_SMEM>>>(gA, gW + (size_t)3 * DM * DM,
                                                    out, out, out, tpos);
}